// round 13
// baseline (speedup 1.0000x reference)
#include <cuda_runtime.h>
#include <cuda_fp16.h>
#include <math.h>
#include <stdint.h>

// ---------------- problem dims ----------------
#define BATCH   65536
#define EDIM    512
#define NH      8
#define DH      64
#define ROWS2   (2*BATCH)      // 131072 sequence rows
#define QKVN    1536
#define CONCATD 1024
#define HIDD    512
#define OUTD    256

// ---------------- scratch (no allocations allowed) ----------------
__device__ __half g_x  [(size_t)ROWS2 * EDIM];   // interleaved fp16 input
__device__ __half g_qkv[(size_t)ROWS2 * QKVN];   // 2B x 1536
__device__ __half g_ctx[(size_t)ROWS2 * EDIM];   // 2B x 512 == B x 1024 (ctx2)
__device__ __half g_h  [(size_t)BATCH * HIDD];   // B x 512
__device__ float  g_o  [(size_t)BATCH * OUTD];   // B x 256 (fp32 for LN)
// fp16 weights, concatenated
#define W_QKV 0
#define W_1   1048576
#define W_2   1572864
__device__ __half g_w[1703936];
__device__ __half g_woT[EDIM * EDIM];            // Wo^T fp16 (512x512)
__device__ __half g_wf [HIDD * CONCATD];         // fused W1@Wo2 (512x1024)
__device__ float  g_bf [HIDD];                   // fused bias
__device__ float  g_zb [EDIM];                   // zero bias (never written)

// ---------------- PTX helpers ----------------
__device__ __forceinline__ uint32_t smem_u32(const void* p) {
    uint32_t a;
    asm("{ .reg .u64 t; cvta.to.shared.u64 t, %1; cvt.u32.u64 %0, t; }" : "=r"(a) : "l"(p));
    return a;
}
__device__ __forceinline__ void cp16(uint32_t dst, const void* src) {
    asm volatile("cp.async.cg.shared.global [%0], [%1], 16;" :: "r"(dst), "l"(src));
}
#define CP_COMMIT() asm volatile("cp.async.commit_group;" ::: "memory")
#define CP_WAIT(n)  asm volatile("cp.async.wait_group %0;" :: "n"(n) : "memory")

__device__ __forceinline__ void ldsm4(uint32_t& r0, uint32_t& r1, uint32_t& r2, uint32_t& r3,
                                      uint32_t addr) {
    asm volatile("ldmatrix.sync.aligned.m8n8.x4.shared.b16 {%0,%1,%2,%3}, [%4];"
                 : "=r"(r0), "=r"(r1), "=r"(r2), "=r"(r3) : "r"(addr));
}

// D += A*B  (m16n8k16, f16 in, f32 accum)
__device__ __forceinline__ void mma_f16(float* d, const uint32_t* a, const uint32_t* b) {
    asm volatile(
        "mma.sync.aligned.m16n8k16.row.col.f32.f16.f16.f32 "
        "{%0,%1,%2,%3}, {%4,%5,%6,%7}, {%8,%9}, {%0,%1,%2,%3};"
        : "+f"(d[0]), "+f"(d[1]), "+f"(d[2]), "+f"(d[3])
        : "r"(a[0]), "r"(a[1]), "r"(a[2]), "r"(a[3]), "r"(b[0]), "r"(b[1]));
}

// ---------------- pre-convert kernels ----------------
__global__ __launch_bounds__(256)
void cvt_kernel(const float* __restrict__ in, __half* __restrict__ out, int n4) {
    int i = blockIdx.x * 256 + threadIdx.x;
    if (i >= n4) return;
    float4 v = *((const float4*)in + i);
    __half2 h0 = __floats2half2_rn(v.x, v.y);
    __half2 h1 = __floats2half2_rn(v.z, v.w);
    __half2* dst = (__half2*)(out + (size_t)i * 4);
    dst[0] = h0;
    dst[1] = h1;
}

// interleave vis/txt into g_x (rows alternate), converting to fp16
__global__ __launch_bounds__(256)
void interleave_kernel(const float* __restrict__ vis, const float* __restrict__ txt,
                       __half* __restrict__ out) {
    int i = blockIdx.x * 256 + threadIdx.x;      // float4 index
    int grow = i >> 7;                            // 128 float4 per row
    int j = i & 127;
    const float* src = (grow & 1) ? txt : vis;
    float4 v = *((const float4*)(src + (size_t)(grow >> 1) * EDIM) + j);
    __half2 h0 = __floats2half2_rn(v.x, v.y);
    __half2 h1 = __floats2half2_rn(v.z, v.w);
    __half2* dst = (__half2*)(out + (size_t)grow * EDIM + j * 4);
    dst[0] = h0;
    dst[1] = h1;
}

// transpose Wo (512x512 f32, torch (out,in)) -> WoT fp16 : WoT[e][j] = Wo[j][e]
__global__ __launch_bounds__(256)
void transpose_wo(const float* __restrict__ wo, __half* __restrict__ woT) {
    int i = blockIdx.x * 256 + threadIdx.x;   // output index e*512 + j
    int e = i >> 9;
    int j = i & 511;
    woT[i] = __float2half_rn(wo[j * EDIM + e]);
}

// fused bias: bf[n] = b1[n] + sum_m W1[n][m] * bo[m % 512]   (all fp32)
__global__ __launch_bounds__(256)
void bfused_kernel(const float* __restrict__ w1, const float* __restrict__ bo,
                   const float* __restrict__ b1, float* __restrict__ bf) {
    int n = blockIdx.x * 256 + threadIdx.x;
    if (n >= HIDD) return;
    const float* row = w1 + (size_t)n * CONCATD;
    float s = 0.f;
    for (int m = 0; m < CONCATD; m++) s += row[m] * bo[m & 511];
    bf[n] = b1[n] + s;
}

// ---------------- fp16 mma.sync GEMM ----------------
// C = A(row stride lda) @ W[N,K]^T + bias.  EPI=1: exact GELU.  HALFOUT: fp16.
// CTA 256x128, BK=64 halves, 3-stage cp.async (ONE barrier per K-tile),
// 8 warps (4m x 2n), warp tile 64x64, ldmatrix.x4 fragment loads.
// 1 CTA/SM (256 threads) -> 255-reg cap, acc 128 + frags 32 fit w/o spills.
#define PADKH 72                       // 64 + 8 halves per smem row (144B)
#define A_HALF (256 * PADKH)           // A tile halves per stage
#define B_HALF (128 * PADKH)           // B tile halves per stage
#define STG_HALF (A_HALF + B_HALF)
#define STG_BYTES (STG_HALF * 2)       // 55296
#define NSTAGE 3
#define SMEM_BYTES (NSTAGE * STG_BYTES)   // 165888

template <int EPI, int HALFOUT>
__global__ __launch_bounds__(256, 1)
void tc_gemm(const __half* __restrict__ A, const __half* __restrict__ W,
             const float* __restrict__ bias, void* __restrict__ Cv,
             int lda, int ldc, int K) {
    extern __shared__ __half smem[];
    const uint32_t smem_u = smem_u32(smem);

    const int tid = threadIdx.x;
    const int wid = tid >> 5;
    const int lane = tid & 31;
    const int g  = lane >> 2;      // 0..7
    const int t4 = lane & 3;       // 0..3
    const int wm = (wid & 3) * 64;    // warp row base (0..192)
    const int wn = (wid >> 2) * 64;   // warp col base (0/64)
    const int m0 = blockIdx.y * 256;
    const int n0 = blockIdx.x * 128;

    // ldmatrix lane offsets (bytes), relative to stage base
    const uint32_t aLane = ((uint32_t)(wm + (lane & 15)) * PADKH + ((lane >> 4) & 1) * 8) * 2;
    const uint32_t bLane = ((uint32_t)(wn + (lane & 7) + ((lane >> 4) & 1) * 8) * PADKH
                            + ((lane >> 3) & 1) * 8) * 2 + A_HALF * 2;

    // global->smem:
    // A: 256 rows, thread t loads row t fully (128B = 8 cp16)
    // B: 128 rows, thread t: row t>>1, half (t&1)*32 halves (64B = 4 cp16)
    const int arow = tid;
    const int brow = tid >> 1;
    const int bh = (tid & 1) * 32;
    const __half* aPtr = A + (size_t)(m0 + arow) * lda;
    const __half* bPtr = W + (size_t)(n0 + brow) * K + bh;
    const uint32_t aDst = smem_u + (arow * PADKH) * 2;
    const uint32_t bDst = smem_u + A_HALF * 2 + (brow * PADKH + bh) * 2;

    float acc[4][8][4];
#pragma unroll
    for (int i = 0; i < 4; i++)
#pragma unroll
        for (int j = 0; j < 8; j++)
#pragma unroll
            for (int r = 0; r < 4; r++) acc[i][j][r] = 0.f;

    const int KT = K >> 6;   // K / 64

    // prologue: stages 0 and 1
#pragma unroll
    for (int s = 0; s < NSTAGE - 1; s++) {
        const __half* ap = aPtr + s * 64;
        const __half* bp = bPtr + s * 64;
        const uint32_t aD = aDst + s * STG_BYTES;
        const uint32_t bD = bDst + s * STG_BYTES;
#pragma unroll
        for (int i = 0; i < 8; i++) cp16(aD + i * 16, ap + i * 8);
#pragma unroll
        for (int i = 0; i < 4; i++) cp16(bD + i * 16, bp + i * 8);
        CP_COMMIT();
    }

    int s = 0;
    for (int kt = 0; kt < KT; kt++) {
        if (kt + 1 < KT) { CP_WAIT(1); } else { CP_WAIT(0); }
        __syncthreads();

        // prefetch kt+2 into stage (s+2)%3 — safe: its readers finished at kt-1.
        if (kt + 2 < KT) {
            int spre = s + 2; if (spre >= NSTAGE) spre -= NSTAGE;
            const __half* ap = aPtr + (kt + 2) * 64;
            const __half* bp = bPtr + (kt + 2) * 64;
            const uint32_t aD = aDst + spre * STG_BYTES;
            const uint32_t bD = bDst + spre * STG_BYTES;
#pragma unroll
            for (int i = 0; i < 8; i++) cp16(aD + i * 16, ap + i * 8);
#pragma unroll
            for (int i = 0; i < 4; i++) cp16(bD + i * 16, bp + i * 8);
            CP_COMMIT();
        }

        const uint32_t aBase = smem_u + s * STG_BYTES + aLane;
        const uint32_t bBase = smem_u + s * STG_BYTES + bLane;

#pragma unroll
        for (int kk = 0; kk < 4; kk++) {
            const uint32_t kOff = kk * 32;   // 16 halves = 32 bytes
            uint32_t af[4][4], bf[8][2];
#pragma unroll
            for (int mt = 0; mt < 4; mt++)
                ldsm4(af[mt][0], af[mt][1], af[mt][2], af[mt][3],
                      aBase + mt * (16 * PADKH * 2) + kOff);
#pragma unroll
            for (int j = 0; j < 4; j++)
                ldsm4(bf[2 * j][0], bf[2 * j][1], bf[2 * j + 1][0], bf[2 * j + 1][1],
                      bBase + j * (16 * PADKH * 2) + kOff);
#pragma unroll
            for (int mt = 0; mt < 4; mt++)
#pragma unroll
                for (int nt = 0; nt < 8; nt++)
                    mma_f16(acc[mt][nt], af[mt], bf[nt]);
        }

        s++; if (s == NSTAGE) s = 0;
    }

    // epilogue
#pragma unroll
    for (int mt = 0; mt < 4; mt++) {
        const size_t r0 = (size_t)(m0 + wm + mt * 16 + g);
        const size_t r1 = r0 + 8;
#pragma unroll
        for (int nt = 0; nt < 8; nt++) {
            const int col = n0 + wn + nt * 8 + t4 * 2;
            const float b0 = __ldg(bias + col);
            const float b1 = __ldg(bias + col + 1);
            float2 v0, v1;
            v0.x = acc[mt][nt][0] + b0;  v0.y = acc[mt][nt][1] + b1;
            v1.x = acc[mt][nt][2] + b0;  v1.y = acc[mt][nt][3] + b1;
            if (EPI == 1) {
                v0.x = 0.5f * v0.x * (1.0f + erff(v0.x * 0.70710678118654752f));
                v0.y = 0.5f * v0.y * (1.0f + erff(v0.y * 0.70710678118654752f));
                v1.x = 0.5f * v1.x * (1.0f + erff(v1.x * 0.70710678118654752f));
                v1.y = 0.5f * v1.y * (1.0f + erff(v1.y * 0.70710678118654752f));
            }
            if (HALFOUT) {
                __half* C = (__half*)Cv;
                *(__half2*)(C + r0 * ldc + col) = __floats2half2_rn(v0.x, v0.y);
                *(__half2*)(C + r1 * ldc + col) = __floats2half2_rn(v1.x, v1.y);
            } else {
                float* C = (float*)Cv;
                *(float2*)(C + r0 * ldc + col) = v0;
                *(float2*)(C + r1 * ldc + col) = v1;
            }
        }
    }
}

// ---------------- attention: one thread per (b, h); seq len 2 ----------------
__device__ __forceinline__ void acc8(float& s, const __half2* p, const __half2* q) {
#pragma unroll
    for (int i = 0; i < 4; i++) {
        float2 a = __half22float2(p[i]);
        float2 b = __half22float2(q[i]);
        s += a.x * b.x + a.y * b.y;
    }
}

__global__ __launch_bounds__(256)
void attn_kernel(const __half* __restrict__ qkv, __half* __restrict__ ctx,
                 float* __restrict__ wout) {
    int t = blockIdx.x * blockDim.x + threadIdx.x;   // b*8 + h
    int b = t >> 3;
    int h = t & 7;

    const __half* base = qkv + (size_t)(2 * b) * QKVN + h * DH;
    const __half2* q0 = (const __half2*)(base);
    const __half2* q1 = (const __half2*)(base + QKVN);
    const __half2* k0 = (const __half2*)(base + 512);
    const __half2* k1 = (const __half2*)(base + 512 + QKVN);
    const __half2* v0 = (const __half2*)(base + 1024);
    const __half2* v1 = (const __half2*)(base + 1024 + QKVN);

    float s00 = 0.f, s01 = 0.f, s10 = 0.f, s11 = 0.f;
#pragma unroll
    for (int d = 0; d < 8; d++) {
        acc8(s00, q0 + d * 4, k0 + d * 4);
        acc8(s01, q0 + d * 4, k1 + d * 4);
        acc8(s10, q1 + d * 4, k0 + d * 4);
        acc8(s11, q1 + d * 4, k1 + d * 4);
    }
    const float sc = 0.125f;   // 1/sqrt(64)
    s00 *= sc; s01 *= sc; s10 *= sc; s11 *= sc;

    float m0 = fmaxf(s00, s01);
    float e00 = expf(s00 - m0), e01 = expf(s01 - m0);
    float r0 = 1.0f / (e00 + e01);
    float a00 = e00 * r0, a01 = e01 * r0;

    float m1 = fmaxf(s10, s11);
    float e10 = expf(s10 - m1), e11 = expf(s11 - m1);
    float r1 = 1.0f / (e10 + e11);
    float a10 = e10 * r1, a11 = e11 * r1;

    __half2* c0 = (__half2*)(ctx + (size_t)(2 * b) * EDIM + h * DH);
    __half2* c1 = (__half2*)(ctx + (size_t)(2 * b) * EDIM + EDIM + h * DH);
#pragma unroll
    for (int d = 0; d < 32; d++) {
        float2 va = __half22float2(v0[d]);
        float2 vb = __half22float2(v1[d]);
        c0[d] = __floats2half2_rn(a00 * va.x + a01 * vb.x, a00 * va.y + a01 * vb.y);
        c1[d] = __floats2half2_rn(a10 * va.x + a11 * vb.x, a10 * va.y + a11 * vb.y);
    }

    // mean over heads: 8 consecutive lanes share a b
    float w0 = a00, w1 = a01, w2 = a10, w3 = a11;
#pragma unroll
    for (int off = 4; off >= 1; off >>= 1) {
        w0 += __shfl_xor_sync(0xffffffffu, w0, off);
        w1 += __shfl_xor_sync(0xffffffffu, w1, off);
        w2 += __shfl_xor_sync(0xffffffffu, w2, off);
        w3 += __shfl_xor_sync(0xffffffffu, w3, off);
    }
    if (h == 0) {
        float4 w;
        w.x = w0 * 0.125f; w.y = w1 * 0.125f; w.z = w2 * 0.125f; w.w = w3 * 0.125f;
        *(float4*)(wout + (size_t)b * 4) = w;
    }
}

// ---------------- layernorm over 256, one block per row ----------------
__global__ __launch_bounds__(256)
void ln_kernel(const float* __restrict__ o, const float* __restrict__ gamma,
               const float* __restrict__ beta, float* __restrict__ out) {
    __shared__ float s1[256];
    __shared__ float s2[256];
    int b = blockIdx.x;
    int j = threadIdx.x;
    float v = o[(size_t)b * OUTD + j];
    s1[j] = v;
    s2[j] = v * v;
    __syncthreads();
#pragma unroll
    for (int st = 128; st > 0; st >>= 1) {
        if (j < st) { s1[j] += s1[j + st]; s2[j] += s2[j + st]; }
        __syncthreads();
    }
    float mu  = s1[0] * (1.0f / OUTD);
    float var = s2[0] * (1.0f / OUTD) - mu * mu;
    float inv = rsqrtf(var + 1e-5f);
    out[(size_t)b * OUTD + j] = (v - mu) * inv * gamma[j] + beta[j];
}

// ---------------- launch ----------------
extern "C" void kernel_launch(void* const* d_in, const int* in_sizes, int n_in,
                              void* d_out, int out_size) {
    const float* vis  = (const float*)d_in[0];
    const float* txt  = (const float*)d_in[1];
    const float* wqkv = (const float*)d_in[2];
    const float* bqkv = (const float*)d_in[3];
    const float* wo   = (const float*)d_in[4];
    const float* bo   = (const float*)d_in[5];
    const float* w1   = (const float*)d_in[6];
    const float* b1   = (const float*)d_in[7];
    const float* w2   = (const float*)d_in[8];
    const float* b2   = (const float*)d_in[9];
    const float* gam  = (const float*)d_in[10];
    const float* bet  = (const float*)d_in[11];

    float* out     = (float*)d_out;
    float* fused   = out;                               // B x 256
    float* weights = out + (size_t)BATCH * OUTD;        // B x 4

    __half *p_x, *p_qkv, *p_ctx, *p_h, *p_w, *p_woT, *p_wf;
    float *p_o, *p_bf, *p_zb;
    cudaGetSymbolAddress((void**)&p_x,   g_x);
    cudaGetSymbolAddress((void**)&p_qkv, g_qkv);
    cudaGetSymbolAddress((void**)&p_ctx, g_ctx);
    cudaGetSymbolAddress((void**)&p_h,   g_h);
    cudaGetSymbolAddress((void**)&p_o,   g_o);
    cudaGetSymbolAddress((void**)&p_w,   g_w);
    cudaGetSymbolAddress((void**)&p_woT, g_woT);
    cudaGetSymbolAddress((void**)&p_wf,  g_wf);
    cudaGetSymbolAddress((void**)&p_bf,  g_bf);
    cudaGetSymbolAddress((void**)&p_zb,  g_zb);

    cudaFuncSetAttribute(tc_gemm<0,1>, cudaFuncAttributeMaxDynamicSharedMemorySize, SMEM_BYTES);
    cudaFuncSetAttribute(tc_gemm<1,1>, cudaFuncAttributeMaxDynamicSharedMemorySize, SMEM_BYTES);
    cudaFuncSetAttribute(tc_gemm<0,0>, cudaFuncAttributeMaxDynamicSharedMemorySize, SMEM_BYTES);

    // 0) pre-convert weights + build interleaved fp16 input
    cvt_kernel<<<(QKVN * EDIM / 4 + 255) / 256, 256>>>(wqkv, p_w + W_QKV, QKVN * EDIM / 4);
    cvt_kernel<<<(HIDD * CONCATD / 4 + 255) / 256, 256>>>(w1, p_w + W_1, HIDD * CONCATD / 4);
    cvt_kernel<<<(OUTD * HIDD / 4 + 255) / 256, 256>>>(w2, p_w + W_2, OUTD * HIDD / 4);
    transpose_wo<<<(EDIM * EDIM) / 256, 256>>>(wo, p_woT);
    interleave_kernel<<<(size_t)ROWS2 * EDIM / 4 / 256, 256>>>(vis, txt, p_x);

    // 1) QKV = X @ Wqkv^T + b   (2B x 1536, fp16 out)  [6th launch -> profiled]
    tc_gemm<0,1><<<dim3(QKVN / 128, ROWS2 / 256), 256, SMEM_BYTES>>>(
        p_x, p_w + W_QKV, bqkv, p_qkv, EDIM, QKVN, EDIM);

    // 1b) fused-weight prep (independent of QKV)
    bfused_kernel<<<(HIDD + 255) / 256, 256>>>(w1, bo, b1, p_bf);
    tc_gemm<0,1><<<dim3(4, 2), 256, SMEM_BYTES>>>(
        p_w + W_1, p_woT, p_zb, p_wf, CONCATD, CONCATD, EDIM);
    tc_gemm<0,1><<<dim3(4, 2), 256, SMEM_BYTES>>>(
        p_w + W_1 + 512, p_woT, p_zb, p_wf + 512, CONCATD, CONCATD, EDIM);

    // 2) attention -> ctx (fp16, B x 1024 view) + weights (B x 4)
    attn_kernel<<<(BATCH * NH) / 256, 256>>>(p_qkv, p_ctx, weights);

    // 3) H = gelu(ctx2 @ Wf^T + bf)   (B x 512, fp16 out)  [out-proj folded in]
    tc_gemm<1,1><<<dim3(HIDD / 128, BATCH / 256), 256, SMEM_BYTES>>>(
        p_ctx, p_wf, p_bf, p_h, CONCATD, HIDD, CONCATD);

    // 4) O = H @ W2^T + b2           (B x 256, fp32 out)
    tc_gemm<0,0><<<dim3(OUTD / 128, BATCH / 256), 256, SMEM_BYTES>>>(
        p_h, p_w + W_2, b2, p_o, HIDD, OUTD, HIDD);

    // 5) layernorm -> fused
    ln_kernel<<<BATCH, 256>>>(p_o, gam, bet, fused);
}

// round 14
// speedup vs baseline: 1.1406x; 1.1406x over previous
#include <cuda_runtime.h>
#include <cuda_fp16.h>
#include <math.h>
#include <stdint.h>

// ---------------- problem dims ----------------
#define BATCH   65536
#define EDIM    512
#define NH      8
#define DH      64
#define ROWS2   (2*BATCH)      // 131072 sequence rows
#define QKVN    1536
#define CONCATD 1024
#define HIDD    512
#define OUTD    256

// ---------------- scratch (no allocations allowed) ----------------
__device__ __half g_x  [(size_t)ROWS2 * EDIM];   // interleaved fp16 input
__device__ __half g_qkv[(size_t)ROWS2 * QKVN];   // 2B x 1536
__device__ __half g_ctx[(size_t)ROWS2 * EDIM];   // 2B x 512 == B x 1024 (ctx2)
__device__ __half g_h  [(size_t)BATCH * HIDD];   // B x 512
// fp16 weights, concatenated
#define W_QKV 0
#define W_1   1048576
#define W_2   1572864
__device__ __half g_w[1703936];
__device__ __half g_woT[EDIM * EDIM];            // Wo^T fp16 (512x512)
__device__ __half g_wf [HIDD * CONCATD];         // fused W1@Wo2 (512x1024)
__device__ float  g_bf [HIDD];                   // fused bias
__device__ float  g_zb [EDIM];                   // zero bias (never written)

// ---------------- PTX helpers ----------------
__device__ __forceinline__ uint32_t smem_u32(const void* p) {
    uint32_t a;
    asm("{ .reg .u64 t; cvta.to.shared.u64 t, %1; cvt.u32.u64 %0, t; }" : "=r"(a) : "l"(p));
    return a;
}
__device__ __forceinline__ void cp16(uint32_t dst, const void* src) {
    asm volatile("cp.async.cg.shared.global [%0], [%1], 16;" :: "r"(dst), "l"(src));
}
#define CP_COMMIT() asm volatile("cp.async.commit_group;" ::: "memory")
#define CP_WAIT(n)  asm volatile("cp.async.wait_group %0;" :: "n"(n) : "memory")

__device__ __forceinline__ void ldsm4(uint32_t& r0, uint32_t& r1, uint32_t& r2, uint32_t& r3,
                                      uint32_t addr) {
    asm volatile("ldmatrix.sync.aligned.m8n8.x4.shared.b16 {%0,%1,%2,%3}, [%4];"
                 : "=r"(r0), "=r"(r1), "=r"(r2), "=r"(r3) : "r"(addr));
}

// D += A*B  (m16n8k16, f16 in, f32 accum)
__device__ __forceinline__ void mma_f16(float* d, const uint32_t* a, const uint32_t* b) {
    asm volatile(
        "mma.sync.aligned.m16n8k16.row.col.f32.f16.f16.f32 "
        "{%0,%1,%2,%3}, {%4,%5,%6,%7}, {%8,%9}, {%0,%1,%2,%3};"
        : "+f"(d[0]), "+f"(d[1]), "+f"(d[2]), "+f"(d[3])
        : "r"(a[0]), "r"(a[1]), "r"(a[2]), "r"(a[3]), "r"(b[0]), "r"(b[1]));
}

// ---------------- pre-convert kernels ----------------
__global__ __launch_bounds__(256)
void cvt_kernel(const float* __restrict__ in, __half* __restrict__ out, int n4) {
    int i = blockIdx.x * 256 + threadIdx.x;
    if (i >= n4) return;
    float4 v = *((const float4*)in + i);
    __half2 h0 = __floats2half2_rn(v.x, v.y);
    __half2 h1 = __floats2half2_rn(v.z, v.w);
    __half2* dst = (__half2*)(out + (size_t)i * 4);
    dst[0] = h0;
    dst[1] = h1;
}

// interleave vis/txt into g_x (rows alternate), converting to fp16
__global__ __launch_bounds__(256)
void interleave_kernel(const float* __restrict__ vis, const float* __restrict__ txt,
                       __half* __restrict__ out) {
    int i = blockIdx.x * 256 + threadIdx.x;      // float4 index
    int grow = i >> 7;                            // 128 float4 per row
    int j = i & 127;
    const float* src = (grow & 1) ? txt : vis;
    float4 v = *((const float4*)(src + (size_t)(grow >> 1) * EDIM) + j);
    __half2 h0 = __floats2half2_rn(v.x, v.y);
    __half2 h1 = __floats2half2_rn(v.z, v.w);
    __half2* dst = (__half2*)(out + (size_t)grow * EDIM + j * 4);
    dst[0] = h0;
    dst[1] = h1;
}

// transpose Wo (512x512 f32, torch (out,in)) -> WoT fp16 : WoT[e][j] = Wo[j][e]
__global__ __launch_bounds__(256)
void transpose_wo(const float* __restrict__ wo, __half* __restrict__ woT) {
    int i = blockIdx.x * 256 + threadIdx.x;   // output index e*512 + j
    int e = i >> 9;
    int j = i & 511;
    woT[i] = __float2half_rn(wo[j * EDIM + e]);
}

// fused bias: bf[n] = b1[n] + sum_m W1[n][m] * bo[m % 512]   (all fp32)
__global__ __launch_bounds__(256)
void bfused_kernel(const float* __restrict__ w1, const float* __restrict__ bo,
                   const float* __restrict__ b1, float* __restrict__ bf) {
    int n = blockIdx.x * 256 + threadIdx.x;
    if (n >= HIDD) return;
    const float* row = w1 + (size_t)n * CONCATD;
    float s = 0.f;
    for (int m = 0; m < CONCATD; m++) s += row[m] * bo[m & 511];
    bf[n] = b1[n] + s;
}

// ---------------- fp16 mma.sync GEMM (round-12 winner, untouched) ----------------
// C = A(row stride lda) @ W[N,K]^T + bias.  EPI=1: exact GELU.  HALFOUT: fp16.
// CTA 128x128, BK=64 halves, 3-stage cp.async (ONE barrier per K-tile),
// 8 warps (2x4), warp tile 64x32, ldmatrix.x4 fragment loads.
#define PADKH 72                       // 64 + 8 halves per smem row (144B)
#define A_HALF (128 * PADKH)           // per operand per stage
#define STG_HALF (2 * A_HALF)
#define STG_BYTES (STG_HALF * 2)       // 36864
#define NSTAGE 3
#define SMEM_BYTES (NSTAGE * STG_BYTES)   // 110592

template <int EPI, int HALFOUT>
__global__ __launch_bounds__(256, 2)
void tc_gemm(const __half* __restrict__ A, const __half* __restrict__ W,
             const float* __restrict__ bias, void* __restrict__ Cv,
             int lda, int ldc, int K) {
    extern __shared__ __half smem[];
    const uint32_t smem_u = smem_u32(smem);

    const int tid = threadIdx.x;
    const int wid = tid >> 5;
    const int lane = tid & 31;
    const int g  = lane >> 2;      // 0..7
    const int t4 = lane & 3;       // 0..3
    const int wm = (wid >> 2) * 64;   // warp row base
    const int wn = (wid & 3) * 32;    // warp col base
    const int m0 = blockIdx.y * 128;
    const int n0 = blockIdx.x * 128;

    const uint32_t aLane = ((uint32_t)(wm + (lane & 15)) * PADKH + ((lane >> 4) & 1) * 8) * 2;
    const uint32_t bLane = ((uint32_t)(wn + (lane & 7) + ((lane >> 4) & 1) * 8) * PADKH
                            + ((lane >> 3) & 1) * 8) * 2 + A_HALF * 2;

    const int lrow = tid >> 1;
    const int lhalf = (tid & 1) * 32;
    const __half* aPtr = A + (size_t)(m0 + lrow) * lda + lhalf;
    const __half* bPtr = W + (size_t)(n0 + lrow) * K + lhalf;
    const uint32_t aDst = smem_u + (lrow * PADKH + lhalf) * 2;
    const uint32_t bDst = aDst + A_HALF * 2;

    float acc[4][4][4];
#pragma unroll
    for (int i = 0; i < 4; i++)
#pragma unroll
        for (int j = 0; j < 4; j++)
#pragma unroll
            for (int r = 0; r < 4; r++) acc[i][j][r] = 0.f;

    const int KT = K >> 6;   // K / 64

#pragma unroll
    for (int s = 0; s < NSTAGE - 1; s++) {
        const __half* ap = aPtr + s * 64;
        const __half* bp = bPtr + s * 64;
        const uint32_t aD = aDst + s * STG_BYTES;
        const uint32_t bD = bDst + s * STG_BYTES;
#pragma unroll
        for (int i = 0; i < 4; i++) cp16(aD + i * 16, ap + i * 8);
#pragma unroll
        for (int i = 0; i < 4; i++) cp16(bD + i * 16, bp + i * 8);
        CP_COMMIT();
    }

    int s = 0;
    for (int kt = 0; kt < KT; kt++) {
        if (kt + 1 < KT) { CP_WAIT(1); } else { CP_WAIT(0); }
        __syncthreads();

        if (kt + 2 < KT) {
            int spre = s + 2; if (spre >= NSTAGE) spre -= NSTAGE;
            const __half* ap = aPtr + (kt + 2) * 64;
            const __half* bp = bPtr + (kt + 2) * 64;
            const uint32_t aD = aDst + spre * STG_BYTES;
            const uint32_t bD = bDst + spre * STG_BYTES;
#pragma unroll
            for (int i = 0; i < 4; i++) cp16(aD + i * 16, ap + i * 8);
#pragma unroll
            for (int i = 0; i < 4; i++) cp16(bD + i * 16, bp + i * 8);
            CP_COMMIT();
        }

        const uint32_t aBase = smem_u + s * STG_BYTES + aLane;
        const uint32_t bBase = smem_u + s * STG_BYTES + bLane;

#pragma unroll
        for (int kk = 0; kk < 4; kk++) {
            const uint32_t kOff = kk * 32;
            uint32_t af[4][4], bf[4][2];
#pragma unroll
            for (int mt = 0; mt < 4; mt++)
                ldsm4(af[mt][0], af[mt][1], af[mt][2], af[mt][3],
                      aBase + mt * (16 * PADKH * 2) + kOff);
            ldsm4(bf[0][0], bf[0][1], bf[1][0], bf[1][1], bBase + kOff);
            ldsm4(bf[2][0], bf[2][1], bf[3][0], bf[3][1],
                  bBase + 16 * PADKH * 2 + kOff);
#pragma unroll
            for (int mt = 0; mt < 4; mt++)
#pragma unroll
                for (int nt = 0; nt < 4; nt++)
                    mma_f16(acc[mt][nt], af[mt], bf[nt]);
        }

        s++; if (s == NSTAGE) s = 0;
    }

#pragma unroll
    for (int mt = 0; mt < 4; mt++) {
        const size_t r0 = (size_t)(m0 + wm + mt * 16 + g);
        const size_t r1 = r0 + 8;
#pragma unroll
        for (int nt = 0; nt < 4; nt++) {
            const int col = n0 + wn + nt * 8 + t4 * 2;
            const float b0 = __ldg(bias + col);
            const float b1 = __ldg(bias + col + 1);
            float2 v0, v1;
            v0.x = acc[mt][nt][0] + b0;  v0.y = acc[mt][nt][1] + b1;
            v1.x = acc[mt][nt][2] + b0;  v1.y = acc[mt][nt][3] + b1;
            if (EPI == 1) {
                v0.x = 0.5f * v0.x * (1.0f + erff(v0.x * 0.70710678118654752f));
                v0.y = 0.5f * v0.y * (1.0f + erff(v0.y * 0.70710678118654752f));
                v1.x = 0.5f * v1.x * (1.0f + erff(v1.x * 0.70710678118654752f));
                v1.y = 0.5f * v1.y * (1.0f + erff(v1.y * 0.70710678118654752f));
            }
            if (HALFOUT) {
                __half* C = (__half*)Cv;
                *(__half2*)(C + r0 * ldc + col) = __floats2half2_rn(v0.x, v0.y);
                *(__half2*)(C + r1 * ldc + col) = __floats2half2_rn(v1.x, v1.y);
            } else {
                float* C = (float*)Cv;
                *(float2*)(C + r0 * ldc + col) = v0;
                *(float2*)(C + r1 * ldc + col) = v1;
            }
        }
    }
}

// ---------------- GEMM4 + LayerNorm fused ----------------
// out[B,256] = LN(H @ W2^T + b2) * gamma + beta.  CTA 128x256 (full LN width),
// 8 warps (2m x 4n), warp tile 64x64.  K = 512.
#define A4_HALF (128 * PADKH)
#define B4_HALF (256 * PADKH)
#define STG4_HALF (A4_HALF + B4_HALF)
#define STG4_BYTES (STG4_HALF * 2)        // 55296
#define SMEM4_BYTES (NSTAGE * STG4_BYTES) // 165888

__global__ __launch_bounds__(256, 1)
void tc_gemm_ln(const __half* __restrict__ A, const __half* __restrict__ W,
                const float* __restrict__ bias, const float* __restrict__ gamma,
                const float* __restrict__ beta, float* __restrict__ out) {
    extern __shared__ __half smem[];
    const uint32_t smem_u = smem_u32(smem);
    const int K = HIDD;      // 512
    const int tid = threadIdx.x;
    const int wid = tid >> 5;
    const int lane = tid & 31;
    const int g  = lane >> 2;
    const int t4 = lane & 3;
    const int wm = (wid >> 2) * 64;   // 0/64
    const int wn = (wid & 3) * 64;    // 0..192
    const int m0 = blockIdx.x * 128;

    const uint32_t aLane = ((uint32_t)(wm + (lane & 15)) * PADKH + ((lane >> 4) & 1) * 8) * 2;
    const uint32_t bLane = ((uint32_t)(wn + (lane & 7) + ((lane >> 4) & 1) * 8) * PADKH
                            + ((lane >> 3) & 1) * 8) * 2 + A4_HALF * 2;

    // A: 128 rows: thread t -> row t>>1, half (t&1)*32 (4 cp16)
    // B: 256 rows: thread t -> row t, full 128B (8 cp16)
    const int arow = tid >> 1;
    const int ahalf = (tid & 1) * 32;
    const __half* aPtr = A + (size_t)(m0 + arow) * K + ahalf;
    const __half* bPtr = W + (size_t)tid * K;
    const uint32_t aDst = smem_u + (arow * PADKH + ahalf) * 2;
    const uint32_t bDst = smem_u + A4_HALF * 2 + (tid * PADKH) * 2;

    float acc[4][8][4];
#pragma unroll
    for (int i = 0; i < 4; i++)
#pragma unroll
        for (int j = 0; j < 8; j++)
#pragma unroll
            for (int r = 0; r < 4; r++) acc[i][j][r] = 0.f;

    const int KT = K >> 6;   // 8

#pragma unroll
    for (int s = 0; s < NSTAGE - 1; s++) {
        const __half* ap = aPtr + s * 64;
        const __half* bp = bPtr + s * 64;
        const uint32_t aD = aDst + s * STG4_BYTES;
        const uint32_t bD = bDst + s * STG4_BYTES;
#pragma unroll
        for (int i = 0; i < 4; i++) cp16(aD + i * 16, ap + i * 8);
#pragma unroll
        for (int i = 0; i < 8; i++) cp16(bD + i * 16, bp + i * 8);
        CP_COMMIT();
    }

    int s = 0;
    for (int kt = 0; kt < KT; kt++) {
        if (kt + 1 < KT) { CP_WAIT(1); } else { CP_WAIT(0); }
        __syncthreads();

        if (kt + 2 < KT) {
            int spre = s + 2; if (spre >= NSTAGE) spre -= NSTAGE;
            const __half* ap = aPtr + (kt + 2) * 64;
            const __half* bp = bPtr + (kt + 2) * 64;
            const uint32_t aD = aDst + spre * STG4_BYTES;
            const uint32_t bD = bDst + spre * STG4_BYTES;
#pragma unroll
            for (int i = 0; i < 4; i++) cp16(aD + i * 16, ap + i * 8);
#pragma unroll
            for (int i = 0; i < 8; i++) cp16(bD + i * 16, bp + i * 8);
            CP_COMMIT();
        }

        const uint32_t aBase = smem_u + s * STG4_BYTES + aLane;
        const uint32_t bBase = smem_u + s * STG4_BYTES + bLane;

#pragma unroll
        for (int kk = 0; kk < 4; kk++) {
            const uint32_t kOff = kk * 32;
            uint32_t af[4][4], bf[8][2];
#pragma unroll
            for (int mt = 0; mt < 4; mt++)
                ldsm4(af[mt][0], af[mt][1], af[mt][2], af[mt][3],
                      aBase + mt * (16 * PADKH * 2) + kOff);
#pragma unroll
            for (int j = 0; j < 4; j++)
                ldsm4(bf[2 * j][0], bf[2 * j][1], bf[2 * j + 1][0], bf[2 * j + 1][1],
                      bBase + j * (16 * PADKH * 2) + kOff);
#pragma unroll
            for (int mt = 0; mt < 4; mt++)
#pragma unroll
                for (int nt = 0; nt < 8; nt++)
                    mma_f16(acc[mt][nt], af[mt], bf[nt]);
        }

        s++; if (s == NSTAGE) s = 0;
    }

    // ---- fused LayerNorm epilogue ----
    __syncthreads();                      // mainloop smem reads done
    float* rs1 = (float*)smem;            // [128][4]
    float* rs2 = rs1 + 128 * 4;           // [128][4]
    const int wnIdx = wid & 3;

    // add bias, per-thread partial sums, lane-reduce over t4, stage to smem
#pragma unroll
    for (int mt = 0; mt < 4; mt++) {
        float s1a = 0.f, s2a = 0.f, s1b = 0.f, s2b = 0.f;
#pragma unroll
        for (int nt = 0; nt < 8; nt++) {
            const int col = wn + nt * 8 + t4 * 2;
            const float b0 = __ldg(bias + col);
            const float b1 = __ldg(bias + col + 1);
            acc[mt][nt][0] += b0; acc[mt][nt][1] += b1;
            acc[mt][nt][2] += b0; acc[mt][nt][3] += b1;
            s1a += acc[mt][nt][0] + acc[mt][nt][1];
            s2a += acc[mt][nt][0] * acc[mt][nt][0] + acc[mt][nt][1] * acc[mt][nt][1];
            s1b += acc[mt][nt][2] + acc[mt][nt][3];
            s2b += acc[mt][nt][2] * acc[mt][nt][2] + acc[mt][nt][3] * acc[mt][nt][3];
        }
#pragma unroll
        for (int off = 1; off <= 2; off <<= 1) {
            s1a += __shfl_xor_sync(0xffffffffu, s1a, off);
            s2a += __shfl_xor_sync(0xffffffffu, s2a, off);
            s1b += __shfl_xor_sync(0xffffffffu, s1b, off);
            s2b += __shfl_xor_sync(0xffffffffu, s2b, off);
        }
        if (t4 == 0) {
            const int r0 = wm + mt * 16 + g;
            rs1[r0 * 4 + wnIdx] = s1a;  rs2[r0 * 4 + wnIdx] = s2a;
            rs1[(r0 + 8) * 4 + wnIdx] = s1b;  rs2[(r0 + 8) * 4 + wnIdx] = s2b;
        }
    }
    __syncthreads();

#pragma unroll
    for (int mt = 0; mt < 4; mt++) {
        const int r0 = wm + mt * 16 + g;
        const int r1 = r0 + 8;
        float su0 = rs1[r0 * 4] + rs1[r0 * 4 + 1] + rs1[r0 * 4 + 2] + rs1[r0 * 4 + 3];
        float sq0 = rs2[r0 * 4] + rs2[r0 * 4 + 1] + rs2[r0 * 4 + 2] + rs2[r0 * 4 + 3];
        float su1 = rs1[r1 * 4] + rs1[r1 * 4 + 1] + rs1[r1 * 4 + 2] + rs1[r1 * 4 + 3];
        float sq1 = rs2[r1 * 4] + rs2[r1 * 4 + 1] + rs2[r1 * 4 + 2] + rs2[r1 * 4 + 3];
        const float mu0 = su0 * (1.0f / OUTD);
        const float iv0 = rsqrtf(sq0 * (1.0f / OUTD) - mu0 * mu0 + 1e-5f);
        const float mu1 = su1 * (1.0f / OUTD);
        const float iv1 = rsqrtf(sq1 * (1.0f / OUTD) - mu1 * mu1 + 1e-5f);
        float* o0 = out + (size_t)(m0 + r0) * OUTD;
        float* o1 = out + (size_t)(m0 + r1) * OUTD;
#pragma unroll
        for (int nt = 0; nt < 8; nt++) {
            const int col = wn + nt * 8 + t4 * 2;
            const float ga0 = __ldg(gamma + col), ga1 = __ldg(gamma + col + 1);
            const float be0 = __ldg(beta + col),  be1 = __ldg(beta + col + 1);
            float2 v0, v1;
            v0.x = (acc[mt][nt][0] - mu0) * iv0 * ga0 + be0;
            v0.y = (acc[mt][nt][1] - mu0) * iv0 * ga1 + be1;
            v1.x = (acc[mt][nt][2] - mu1) * iv1 * ga0 + be0;
            v1.y = (acc[mt][nt][3] - mu1) * iv1 * ga1 + be1;
            *(float2*)(o0 + col) = v0;
            *(float2*)(o1 + col) = v1;
        }
    }
}

// ---------------- attention: one thread per (b, h); seq len 2 ----------------
__device__ __forceinline__ void acc8(float& s, const __half2* p, const __half2* q) {
#pragma unroll
    for (int i = 0; i < 4; i++) {
        float2 a = __half22float2(p[i]);
        float2 b = __half22float2(q[i]);
        s += a.x * b.x + a.y * b.y;
    }
}

__global__ __launch_bounds__(256)
void attn_kernel(const __half* __restrict__ qkv, __half* __restrict__ ctx,
                 float* __restrict__ wout) {
    int t = blockIdx.x * blockDim.x + threadIdx.x;   // b*8 + h
    int b = t >> 3;
    int h = t & 7;

    const __half* base = qkv + (size_t)(2 * b) * QKVN + h * DH;
    const __half2* q0 = (const __half2*)(base);
    const __half2* q1 = (const __half2*)(base + QKVN);
    const __half2* k0 = (const __half2*)(base + 512);
    const __half2* k1 = (const __half2*)(base + 512 + QKVN);
    const __half2* v0 = (const __half2*)(base + 1024);
    const __half2* v1 = (const __half2*)(base + 1024 + QKVN);

    float s00 = 0.f, s01 = 0.f, s10 = 0.f, s11 = 0.f;
#pragma unroll
    for (int d = 0; d < 8; d++) {
        acc8(s00, q0 + d * 4, k0 + d * 4);
        acc8(s01, q0 + d * 4, k1 + d * 4);
        acc8(s10, q1 + d * 4, k0 + d * 4);
        acc8(s11, q1 + d * 4, k1 + d * 4);
    }
    const float sc = 0.125f;   // 1/sqrt(64)
    s00 *= sc; s01 *= sc; s10 *= sc; s11 *= sc;

    float m0 = fmaxf(s00, s01);
    float e00 = expf(s00 - m0), e01 = expf(s01 - m0);
    float r0 = 1.0f / (e00 + e01);
    float a00 = e00 * r0, a01 = e01 * r0;

    float m1 = fmaxf(s10, s11);
    float e10 = expf(s10 - m1), e11 = expf(s11 - m1);
    float r1 = 1.0f / (e10 + e11);
    float a10 = e10 * r1, a11 = e11 * r1;

    __half2* c0 = (__half2*)(ctx + (size_t)(2 * b) * EDIM + h * DH);
    __half2* c1 = (__half2*)(ctx + (size_t)(2 * b) * EDIM + EDIM + h * DH);
#pragma unroll
    for (int d = 0; d < 32; d++) {
        float2 va = __half22float2(v0[d]);
        float2 vb = __half22float2(v1[d]);
        c0[d] = __floats2half2_rn(a00 * va.x + a01 * vb.x, a00 * va.y + a01 * vb.y);
        c1[d] = __floats2half2_rn(a10 * va.x + a11 * vb.x, a10 * va.y + a11 * vb.y);
    }

    // mean over heads: 8 consecutive lanes share a b
    float w0 = a00, w1 = a01, w2 = a10, w3 = a11;
#pragma unroll
    for (int off = 4; off >= 1; off >>= 1) {
        w0 += __shfl_xor_sync(0xffffffffu, w0, off);
        w1 += __shfl_xor_sync(0xffffffffu, w1, off);
        w2 += __shfl_xor_sync(0xffffffffu, w2, off);
        w3 += __shfl_xor_sync(0xffffffffu, w3, off);
    }
    if (h == 0) {
        float4 w;
        w.x = w0 * 0.125f; w.y = w1 * 0.125f; w.z = w2 * 0.125f; w.w = w3 * 0.125f;
        *(float4*)(wout + (size_t)b * 4) = w;
    }
}

// ---------------- launch ----------------
extern "C" void kernel_launch(void* const* d_in, const int* in_sizes, int n_in,
                              void* d_out, int out_size) {
    const float* vis  = (const float*)d_in[0];
    const float* txt  = (const float*)d_in[1];
    const float* wqkv = (const float*)d_in[2];
    const float* bqkv = (const float*)d_in[3];
    const float* wo   = (const float*)d_in[4];
    const float* bo   = (const float*)d_in[5];
    const float* w1   = (const float*)d_in[6];
    const float* b1   = (const float*)d_in[7];
    const float* w2   = (const float*)d_in[8];
    const float* b2   = (const float*)d_in[9];
    const float* gam  = (const float*)d_in[10];
    const float* bet  = (const float*)d_in[11];

    float* out     = (float*)d_out;
    float* fused   = out;                               // B x 256
    float* weights = out + (size_t)BATCH * OUTD;        // B x 4

    __half *p_x, *p_qkv, *p_ctx, *p_h, *p_w, *p_woT, *p_wf;
    float *p_bf, *p_zb;
    cudaGetSymbolAddress((void**)&p_x,   g_x);
    cudaGetSymbolAddress((void**)&p_qkv, g_qkv);
    cudaGetSymbolAddress((void**)&p_ctx, g_ctx);
    cudaGetSymbolAddress((void**)&p_h,   g_h);
    cudaGetSymbolAddress((void**)&p_w,   g_w);
    cudaGetSymbolAddress((void**)&p_woT, g_woT);
    cudaGetSymbolAddress((void**)&p_wf,  g_wf);
    cudaGetSymbolAddress((void**)&p_bf,  g_bf);
    cudaGetSymbolAddress((void**)&p_zb,  g_zb);

    cudaFuncSetAttribute(tc_gemm<0,1>, cudaFuncAttributeMaxDynamicSharedMemorySize, SMEM_BYTES);
    cudaFuncSetAttribute(tc_gemm<1,1>, cudaFuncAttributeMaxDynamicSharedMemorySize, SMEM_BYTES);
    cudaFuncSetAttribute(tc_gemm_ln, cudaFuncAttributeMaxDynamicSharedMemorySize, SMEM4_BYTES);

    // 0) pre-convert weights + build interleaved fp16 input + fused weight prep
    cvt_kernel<<<(QKVN * EDIM / 4 + 255) / 256, 256>>>(wqkv, p_w + W_QKV, QKVN * EDIM / 4);
    cvt_kernel<<<(HIDD * CONCATD / 4 + 255) / 256, 256>>>(w1, p_w + W_1, HIDD * CONCATD / 4);
    cvt_kernel<<<(OUTD * HIDD / 4 + 255) / 256, 256>>>(w2, p_w + W_2, OUTD * HIDD / 4);
    transpose_wo<<<(EDIM * EDIM) / 256, 256>>>(wo, p_woT);
    interleave_kernel<<<(size_t)ROWS2 * EDIM / 4 / 256, 256>>>(vis, txt, p_x);
    bfused_kernel<<<(HIDD + 255) / 256, 256>>>(w1, bo, b1, p_bf);

    // 0b) Wf[:, s*512 + e] = W1[:, s*512:(s+1)*512] @ Wo   (s = 0, 1), fp16 out
    tc_gemm<0,1><<<dim3(4, 4), 256, SMEM_BYTES>>>(
        p_w + W_1, p_woT, p_zb, p_wf, CONCATD, CONCATD, EDIM);
    tc_gemm<0,1><<<dim3(4, 4), 256, SMEM_BYTES>>>(
        p_w + W_1 + 512, p_woT, p_zb, p_wf + 512, CONCATD, CONCATD, EDIM);

    // 1) QKV = X @ Wqkv^T + b        (2B x 1536, fp16 out)
    tc_gemm<0,1><<<dim3(QKVN / 128, ROWS2 / 128), 256, SMEM_BYTES>>>(
        p_x, p_w + W_QKV, bqkv, p_qkv, EDIM, QKVN, EDIM);

    // 2) attention -> ctx (fp16, B x 1024 view) + weights (B x 4)
    attn_kernel<<<(BATCH * NH) / 256, 256>>>(p_qkv, p_ctx, weights);

    // 3) H = gelu(ctx2 @ Wf^T + bf)   (B x 512, fp16 out)  [out-proj folded in]
    tc_gemm<1,1><<<dim3(HIDD / 128, BATCH / 128), 256, SMEM_BYTES>>>(
        p_ctx, p_wf, p_bf, p_h, CONCATD, HIDD, CONCATD);

    // 4) fused = LN(H @ W2^T + b2) * gamma + beta   (B x 256, fp32 out)
    tc_gemm_ln<<<BATCH / 128, 256, SMEM4_BYTES>>>(
        p_h, p_w + W_2, b2, gam, bet, fused);
}

// round 15
// speedup vs baseline: 1.3909x; 1.2194x over previous
#include <cuda_runtime.h>
#include <cuda_fp16.h>
#include <math.h>
#include <stdint.h>

// ---------------- problem dims ----------------
#define BATCH   65536
#define EDIM    512
#define NH      8
#define DH      64
#define ROWS2   (2*BATCH)      // 131072 sequence rows
#define QKVN    1536
#define CONCATD 1024
#define HIDD    512
#define OUTD    256

// ---------------- scratch (no allocations allowed) ----------------
__device__ __half g_x  [(size_t)ROWS2 * EDIM];   // interleaved fp16 input
__device__ __half g_qkv[(size_t)ROWS2 * QKVN];   // 2B x 1536
__device__ __half g_ctx[(size_t)ROWS2 * EDIM];   // 2B x 512 == B x 1024 (ctx2)
__device__ __half g_h  [(size_t)BATCH * HIDD];   // B x 512
// fp16 weights, concatenated
#define W_QKV 0
#define W_1   1048576
#define W_2   1572864
__device__ __half g_w[1703936];
__device__ __half g_woT[EDIM * EDIM];            // Wo^T fp16 (512x512)
__device__ __half g_wf [HIDD * CONCATD];         // fused W1@Wo2 (512x1024)
__device__ float  g_bf [HIDD];                   // fused bias
__device__ float  g_zb [EDIM];                   // zero bias (never written)

// ---------------- PTX helpers ----------------
__device__ __forceinline__ uint32_t smem_u32(const void* p) {
    uint32_t a;
    asm("{ .reg .u64 t; cvta.to.shared.u64 t, %1; cvt.u32.u64 %0, t; }" : "=r"(a) : "l"(p));
    return a;
}
__device__ __forceinline__ void cp16(uint32_t dst, const void* src) {
    asm volatile("cp.async.cg.shared.global [%0], [%1], 16;" :: "r"(dst), "l"(src));
}
#define CP_COMMIT() asm volatile("cp.async.commit_group;" ::: "memory")
#define CP_WAIT(n)  asm volatile("cp.async.wait_group %0;" :: "n"(n) : "memory")

__device__ __forceinline__ void ldsm4(uint32_t& r0, uint32_t& r1, uint32_t& r2, uint32_t& r3,
                                      uint32_t addr) {
    asm volatile("ldmatrix.sync.aligned.m8n8.x4.shared.b16 {%0,%1,%2,%3}, [%4];"
                 : "=r"(r0), "=r"(r1), "=r"(r2), "=r"(r3) : "r"(addr));
}

// D += A*B  (m16n8k16, f16 in, f32 accum)
__device__ __forceinline__ void mma_f16(float* d, const uint32_t* a, const uint32_t* b) {
    asm volatile(
        "mma.sync.aligned.m16n8k16.row.col.f32.f16.f16.f32 "
        "{%0,%1,%2,%3}, {%4,%5,%6,%7}, {%8,%9}, {%0,%1,%2,%3};"
        : "+f"(d[0]), "+f"(d[1]), "+f"(d[2]), "+f"(d[3])
        : "r"(a[0]), "r"(a[1]), "r"(a[2]), "r"(a[3]), "r"(b[0]), "r"(b[1]));
}

// ---------------- pre-convert kernels ----------------
__global__ __launch_bounds__(256)
void cvt_kernel(const float* __restrict__ in, __half* __restrict__ out, int n4) {
    int i = blockIdx.x * 256 + threadIdx.x;
    if (i >= n4) return;
    float4 v = *((const float4*)in + i);
    __half2 h0 = __floats2half2_rn(v.x, v.y);
    __half2 h1 = __floats2half2_rn(v.z, v.w);
    __half2* dst = (__half2*)(out + (size_t)i * 4);
    dst[0] = h0;
    dst[1] = h1;
}

// interleave vis/txt into g_x (rows alternate), converting to fp16
__global__ __launch_bounds__(256)
void interleave_kernel(const float* __restrict__ vis, const float* __restrict__ txt,
                       __half* __restrict__ out) {
    int i = blockIdx.x * 256 + threadIdx.x;      // float4 index
    int grow = i >> 7;                            // 128 float4 per row
    int j = i & 127;
    const float* src = (grow & 1) ? txt : vis;
    float4 v = *((const float4*)(src + (size_t)(grow >> 1) * EDIM) + j);
    __half2 h0 = __floats2half2_rn(v.x, v.y);
    __half2 h1 = __floats2half2_rn(v.z, v.w);
    __half2* dst = (__half2*)(out + (size_t)grow * EDIM + j * 4);
    dst[0] = h0;
    dst[1] = h1;
}

// transpose Wo (512x512 f32, torch (out,in)) -> WoT fp16 : WoT[e][j] = Wo[j][e]
__global__ __launch_bounds__(256)
void transpose_wo(const float* __restrict__ wo, __half* __restrict__ woT) {
    int i = blockIdx.x * 256 + threadIdx.x;   // output index e*512 + j
    int e = i >> 9;
    int j = i & 511;
    woT[i] = __float2half_rn(wo[j * EDIM + e]);
}

// fused bias: bf[n] = b1[n] + sum_m W1[n][m] * bo[m % 512]   (all fp32)
__global__ __launch_bounds__(256)
void bfused_kernel(const float* __restrict__ w1, const float* __restrict__ bo,
                   const float* __restrict__ b1, float* __restrict__ bf) {
    int n = blockIdx.x * 256 + threadIdx.x;
    if (n >= HIDD) return;
    const float* row = w1 + (size_t)n * CONCATD;
    float s = 0.f;
    for (int m = 0; m < CONCATD; m++) s += row[m] * bo[m & 511];
    bf[n] = b1[n] + s;
}

// ---------------- fp16 mma.sync GEMM ----------------
// C = A(row stride lda) @ W[N,K]^T + bias.  EPI=1: exact GELU.  HALFOUT: fp16.
// CTA 128x128, BK=64 halves, 3-stage cp.async (ONE barrier per K-tile),
// 8 warps (2x4), warp tile 64x32, ldmatrix.x4, B-fragment double buffered.
#define PADKH 72                       // 64 + 8 halves per smem row (144B)
#define A_HALF (128 * PADKH)           // per operand per stage
#define STG_HALF (2 * A_HALF)
#define STG_BYTES (STG_HALF * 2)       // 36864
#define NSTAGE 3
#define SMEM_BYTES (NSTAGE * STG_BYTES)   // 110592

template <int EPI, int HALFOUT>
__global__ __launch_bounds__(256, 2)
void tc_gemm(const __half* __restrict__ A, const __half* __restrict__ W,
             const float* __restrict__ bias, void* __restrict__ Cv,
             int lda, int ldc, int K) {
    extern __shared__ __half smem[];
    const uint32_t smem_u = smem_u32(smem);

    const int tid = threadIdx.x;
    const int wid = tid >> 5;
    const int lane = tid & 31;
    const int g  = lane >> 2;      // 0..7
    const int t4 = lane & 3;       // 0..3
    const int wm = (wid >> 2) * 64;   // warp row base
    const int wn = (wid & 3) * 32;    // warp col base
    const int m0 = blockIdx.y * 128;
    const int n0 = blockIdx.x * 128;

    const uint32_t aLane = ((uint32_t)(wm + (lane & 15)) * PADKH + ((lane >> 4) & 1) * 8) * 2;
    const uint32_t bLane = ((uint32_t)(wn + (lane & 7) + ((lane >> 4) & 1) * 8) * PADKH
                            + ((lane >> 3) & 1) * 8) * 2 + A_HALF * 2;

    const int lrow = tid >> 1;
    const int lhalf = (tid & 1) * 32;
    const __half* aPtr = A + (size_t)(m0 + lrow) * lda + lhalf;
    const __half* bPtr = W + (size_t)(n0 + lrow) * K + lhalf;
    const uint32_t aDst = smem_u + (lrow * PADKH + lhalf) * 2;
    const uint32_t bDst = aDst + A_HALF * 2;

    float acc[4][4][4];
#pragma unroll
    for (int i = 0; i < 4; i++)
#pragma unroll
        for (int j = 0; j < 4; j++)
#pragma unroll
            for (int r = 0; r < 4; r++) acc[i][j][r] = 0.f;

    const int KT = K >> 6;   // K / 64

#pragma unroll
    for (int s = 0; s < NSTAGE - 1; s++) {
        const __half* ap = aPtr + s * 64;
        const __half* bp = bPtr + s * 64;
        const uint32_t aD = aDst + s * STG_BYTES;
        const uint32_t bD = bDst + s * STG_BYTES;
#pragma unroll
        for (int i = 0; i < 4; i++) cp16(aD + i * 16, ap + i * 8);
#pragma unroll
        for (int i = 0; i < 4; i++) cp16(bD + i * 16, bp + i * 8);
        CP_COMMIT();
    }

    int s = 0;
    for (int kt = 0; kt < KT; kt++) {
        if (kt + 1 < KT) { CP_WAIT(1); } else { CP_WAIT(0); }
        __syncthreads();

        if (kt + 2 < KT) {
            int spre = s + 2; if (spre >= NSTAGE) spre -= NSTAGE;
            const __half* ap = aPtr + (kt + 2) * 64;
            const __half* bp = bPtr + (kt + 2) * 64;
            const uint32_t aD = aDst + spre * STG_BYTES;
            const uint32_t bD = bDst + spre * STG_BYTES;
#pragma unroll
            for (int i = 0; i < 4; i++) cp16(aD + i * 16, ap + i * 8);
#pragma unroll
            for (int i = 0; i < 4; i++) cp16(bD + i * 16, bp + i * 8);
            CP_COMMIT();
        }

        const uint32_t aBase = smem_u + s * STG_BYTES + aLane;
        const uint32_t bBase = smem_u + s * STG_BYTES + bLane;

        // B fragments double-buffered across kk (A single-buffered)
        uint32_t bf[2][4][2];
        ldsm4(bf[0][0][0], bf[0][0][1], bf[0][1][0], bf[0][1][1], bBase);
        ldsm4(bf[0][2][0], bf[0][2][1], bf[0][3][0], bf[0][3][1],
              bBase + 16 * PADKH * 2);
#pragma unroll
        for (int kk = 0; kk < 4; kk++) {
            const int cur = kk & 1, nxt = cur ^ 1;
            const uint32_t kOff = kk * 32;
            uint32_t af[4][4];
#pragma unroll
            for (int mt = 0; mt < 4; mt++)
                ldsm4(af[mt][0], af[mt][1], af[mt][2], af[mt][3],
                      aBase + mt * (16 * PADKH * 2) + kOff);
            if (kk < 3) {
                const uint32_t kn = (kk + 1) * 32;
                ldsm4(bf[nxt][0][0], bf[nxt][0][1], bf[nxt][1][0], bf[nxt][1][1],
                      bBase + kn);
                ldsm4(bf[nxt][2][0], bf[nxt][2][1], bf[nxt][3][0], bf[nxt][3][1],
                      bBase + 16 * PADKH * 2 + kn);
            }
#pragma unroll
            for (int mt = 0; mt < 4; mt++)
#pragma unroll
                for (int nt = 0; nt < 4; nt++)
                    mma_f16(acc[mt][nt], af[mt], bf[cur][nt]);
        }

        s++; if (s == NSTAGE) s = 0;
    }

#pragma unroll
    for (int mt = 0; mt < 4; mt++) {
        const size_t r0 = (size_t)(m0 + wm + mt * 16 + g);
        const size_t r1 = r0 + 8;
#pragma unroll
        for (int nt = 0; nt < 4; nt++) {
            const int col = n0 + wn + nt * 8 + t4 * 2;
            const float b0 = __ldg(bias + col);
            const float b1 = __ldg(bias + col + 1);
            float2 v0, v1;
            v0.x = acc[mt][nt][0] + b0;  v0.y = acc[mt][nt][1] + b1;
            v1.x = acc[mt][nt][2] + b0;  v1.y = acc[mt][nt][3] + b1;
            if (EPI == 1) {
                v0.x = 0.5f * v0.x * (1.0f + erff(v0.x * 0.70710678118654752f));
                v0.y = 0.5f * v0.y * (1.0f + erff(v0.y * 0.70710678118654752f));
                v1.x = 0.5f * v1.x * (1.0f + erff(v1.x * 0.70710678118654752f));
                v1.y = 0.5f * v1.y * (1.0f + erff(v1.y * 0.70710678118654752f));
            }
            if (HALFOUT) {
                __half* C = (__half*)Cv;
                *(__half2*)(C + r0 * ldc + col) = __floats2half2_rn(v0.x, v0.y);
                *(__half2*)(C + r1 * ldc + col) = __floats2half2_rn(v1.x, v1.y);
            } else {
                float* C = (float*)Cv;
                *(float2*)(C + r0 * ldc + col) = v0;
                *(float2*)(C + r1 * ldc + col) = v1;
            }
        }
    }
}

// ---------------- GEMM4 + LayerNorm fused ----------------
// out[B,256] = LN(H @ W2^T + b2) * gamma + beta.  CTA 128x256 (full LN width),
// 8 warps (2m x 4n), warp tile 64x64.  K = 512.
#define A4_HALF (128 * PADKH)
#define B4_HALF (256 * PADKH)
#define STG4_HALF (A4_HALF + B4_HALF)
#define STG4_BYTES (STG4_HALF * 2)        // 55296
#define SMEM4_BYTES (NSTAGE * STG4_BYTES) // 165888

__global__ __launch_bounds__(256, 1)
void tc_gemm_ln(const __half* __restrict__ A, const __half* __restrict__ W,
                const float* __restrict__ bias, const float* __restrict__ gamma,
                const float* __restrict__ beta, float* __restrict__ out) {
    extern __shared__ __half smem[];
    const uint32_t smem_u = smem_u32(smem);
    const int K = HIDD;      // 512
    const int tid = threadIdx.x;
    const int wid = tid >> 5;
    const int lane = tid & 31;
    const int g  = lane >> 2;
    const int t4 = lane & 3;
    const int wm = (wid >> 2) * 64;   // 0/64
    const int wn = (wid & 3) * 64;    // 0..192
    const int m0 = blockIdx.x * 128;

    const uint32_t aLane = ((uint32_t)(wm + (lane & 15)) * PADKH + ((lane >> 4) & 1) * 8) * 2;
    const uint32_t bLane = ((uint32_t)(wn + (lane & 7) + ((lane >> 4) & 1) * 8) * PADKH
                            + ((lane >> 3) & 1) * 8) * 2 + A4_HALF * 2;

    const int arow = tid >> 1;
    const int ahalf = (tid & 1) * 32;
    const __half* aPtr = A + (size_t)(m0 + arow) * K + ahalf;
    const __half* bPtr = W + (size_t)tid * K;
    const uint32_t aDst = smem_u + (arow * PADKH + ahalf) * 2;
    const uint32_t bDst = smem_u + A4_HALF * 2 + (tid * PADKH) * 2;

    float acc[4][8][4];
#pragma unroll
    for (int i = 0; i < 4; i++)
#pragma unroll
        for (int j = 0; j < 8; j++)
#pragma unroll
            for (int r = 0; r < 4; r++) acc[i][j][r] = 0.f;

    const int KT = K >> 6;   // 8

#pragma unroll
    for (int s = 0; s < NSTAGE - 1; s++) {
        const __half* ap = aPtr + s * 64;
        const __half* bp = bPtr + s * 64;
        const uint32_t aD = aDst + s * STG4_BYTES;
        const uint32_t bD = bDst + s * STG4_BYTES;
#pragma unroll
        for (int i = 0; i < 4; i++) cp16(aD + i * 16, ap + i * 8);
#pragma unroll
        for (int i = 0; i < 8; i++) cp16(bD + i * 16, bp + i * 8);
        CP_COMMIT();
    }

    int s = 0;
    for (int kt = 0; kt < KT; kt++) {
        if (kt + 1 < KT) { CP_WAIT(1); } else { CP_WAIT(0); }
        __syncthreads();

        if (kt + 2 < KT) {
            int spre = s + 2; if (spre >= NSTAGE) spre -= NSTAGE;
            const __half* ap = aPtr + (kt + 2) * 64;
            const __half* bp = bPtr + (kt + 2) * 64;
            const uint32_t aD = aDst + spre * STG4_BYTES;
            const uint32_t bD = bDst + spre * STG4_BYTES;
#pragma unroll
            for (int i = 0; i < 4; i++) cp16(aD + i * 16, ap + i * 8);
#pragma unroll
            for (int i = 0; i < 8; i++) cp16(bD + i * 16, bp + i * 8);
            CP_COMMIT();
        }

        const uint32_t aBase = smem_u + s * STG4_BYTES + aLane;
        const uint32_t bBase = smem_u + s * STG4_BYTES + bLane;

#pragma unroll
        for (int kk = 0; kk < 4; kk++) {
            const uint32_t kOff = kk * 32;
            uint32_t af[4][4], bf[8][2];
#pragma unroll
            for (int mt = 0; mt < 4; mt++)
                ldsm4(af[mt][0], af[mt][1], af[mt][2], af[mt][3],
                      aBase + mt * (16 * PADKH * 2) + kOff);
#pragma unroll
            for (int j = 0; j < 4; j++)
                ldsm4(bf[2 * j][0], bf[2 * j][1], bf[2 * j + 1][0], bf[2 * j + 1][1],
                      bBase + j * (16 * PADKH * 2) + kOff);
#pragma unroll
            for (int mt = 0; mt < 4; mt++)
#pragma unroll
                for (int nt = 0; nt < 8; nt++)
                    mma_f16(acc[mt][nt], af[mt], bf[nt]);
        }

        s++; if (s == NSTAGE) s = 0;
    }

    // ---- fused LayerNorm epilogue ----
    __syncthreads();
    float* rs1 = (float*)smem;            // [128][4]
    float* rs2 = rs1 + 128 * 4;           // [128][4]
    const int wnIdx = wid & 3;

#pragma unroll
    for (int mt = 0; mt < 4; mt++) {
        float s1a = 0.f, s2a = 0.f, s1b = 0.f, s2b = 0.f;
#pragma unroll
        for (int nt = 0; nt < 8; nt++) {
            const int col = wn + nt * 8 + t4 * 2;
            const float b0 = __ldg(bias + col);
            const float b1 = __ldg(bias + col + 1);
            acc[mt][nt][0] += b0; acc[mt][nt][1] += b1;
            acc[mt][nt][2] += b0; acc[mt][nt][3] += b1;
            s1a += acc[mt][nt][0] + acc[mt][nt][1];
            s2a += acc[mt][nt][0] * acc[mt][nt][0] + acc[mt][nt][1] * acc[mt][nt][1];
            s1b += acc[mt][nt][2] + acc[mt][nt][3];
            s2b += acc[mt][nt][2] * acc[mt][nt][2] + acc[mt][nt][3] * acc[mt][nt][3];
        }
#pragma unroll
        for (int off = 1; off <= 2; off <<= 1) {
            s1a += __shfl_xor_sync(0xffffffffu, s1a, off);
            s2a += __shfl_xor_sync(0xffffffffu, s2a, off);
            s1b += __shfl_xor_sync(0xffffffffu, s1b, off);
            s2b += __shfl_xor_sync(0xffffffffu, s2b, off);
        }
        if (t4 == 0) {
            const int r0 = wm + mt * 16 + g;
            rs1[r0 * 4 + wnIdx] = s1a;  rs2[r0 * 4 + wnIdx] = s2a;
            rs1[(r0 + 8) * 4 + wnIdx] = s1b;  rs2[(r0 + 8) * 4 + wnIdx] = s2b;
        }
    }
    __syncthreads();

#pragma unroll
    for (int mt = 0; mt < 4; mt++) {
        const int r0 = wm + mt * 16 + g;
        const int r1 = r0 + 8;
        float su0 = rs1[r0 * 4] + rs1[r0 * 4 + 1] + rs1[r0 * 4 + 2] + rs1[r0 * 4 + 3];
        float sq0 = rs2[r0 * 4] + rs2[r0 * 4 + 1] + rs2[r0 * 4 + 2] + rs2[r0 * 4 + 3];
        float su1 = rs1[r1 * 4] + rs1[r1 * 4 + 1] + rs1[r1 * 4 + 2] + rs1[r1 * 4 + 3];
        float sq1 = rs2[r1 * 4] + rs2[r1 * 4 + 1] + rs2[r1 * 4 + 2] + rs2[r1 * 4 + 3];
        const float mu0 = su0 * (1.0f / OUTD);
        const float iv0 = rsqrtf(sq0 * (1.0f / OUTD) - mu0 * mu0 + 1e-5f);
        const float mu1 = su1 * (1.0f / OUTD);
        const float iv1 = rsqrtf(sq1 * (1.0f / OUTD) - mu1 * mu1 + 1e-5f);
        float* o0 = out + (size_t)(m0 + r0) * OUTD;
        float* o1 = out + (size_t)(m0 + r1) * OUTD;
#pragma unroll
        for (int nt = 0; nt < 8; nt++) {
            const int col = wn + nt * 8 + t4 * 2;
            const float ga0 = __ldg(gamma + col), ga1 = __ldg(gamma + col + 1);
            const float be0 = __ldg(beta + col),  be1 = __ldg(beta + col + 1);
            float2 v0, v1;
            v0.x = (acc[mt][nt][0] - mu0) * iv0 * ga0 + be0;
            v0.y = (acc[mt][nt][1] - mu0) * iv0 * ga1 + be1;
            v1.x = (acc[mt][nt][2] - mu1) * iv1 * ga0 + be0;
            v1.y = (acc[mt][nt][3] - mu1) * iv1 * ga1 + be1;
            *(float2*)(o0 + col) = v0;
            *(float2*)(o1 + col) = v1;
        }
    }
}

// ---------------- attention: one thread per (b, h); 16B vectorized ----------
__device__ __forceinline__ float dot8h(uint4 a, uint4 b) {
    float s = 0.f;
    const __half2* pa = (const __half2*)&a;
    const __half2* pb = (const __half2*)&b;
#pragma unroll
    for (int i = 0; i < 4; i++) {
        float2 x = __half22float2(pa[i]);
        float2 y = __half22float2(pb[i]);
        s += x.x * y.x + x.y * y.y;
    }
    return s;
}

__global__ __launch_bounds__(256)
void attn_kernel(const __half* __restrict__ qkv, __half* __restrict__ ctx,
                 float* __restrict__ wout) {
    int t = blockIdx.x * blockDim.x + threadIdx.x;   // b*8 + h
    int b = t >> 3;
    int h = t & 7;

    const __half* base = qkv + (size_t)(2 * b) * QKVN + h * DH;
    const uint4* q0 = (const uint4*)(base);
    const uint4* q1 = (const uint4*)(base + QKVN);
    const uint4* k0 = (const uint4*)(base + 512);
    const uint4* k1 = (const uint4*)(base + 512 + QKVN);
    const uint4* v0 = (const uint4*)(base + 1024);
    const uint4* v1 = (const uint4*)(base + 1024 + QKVN);

    float s00 = 0.f, s01 = 0.f, s10 = 0.f, s11 = 0.f;
#pragma unroll
    for (int d = 0; d < 8; d++) {
        uint4 qa = q0[d], qb = q1[d], ka = k0[d], kb = k1[d];
        s00 += dot8h(qa, ka);
        s01 += dot8h(qa, kb);
        s10 += dot8h(qb, ka);
        s11 += dot8h(qb, kb);
    }
    const float sc = 0.125f;   // 1/sqrt(64)
    s00 *= sc; s01 *= sc; s10 *= sc; s11 *= sc;

    float m0 = fmaxf(s00, s01);
    float e00 = expf(s00 - m0), e01 = expf(s01 - m0);
    float r0 = 1.0f / (e00 + e01);
    float a00 = e00 * r0, a01 = e01 * r0;

    float m1 = fmaxf(s10, s11);
    float e10 = expf(s10 - m1), e11 = expf(s11 - m1);
    float r1 = 1.0f / (e10 + e11);
    float a10 = e10 * r1, a11 = e11 * r1;

    uint4* c0 = (uint4*)(ctx + (size_t)(2 * b) * EDIM + h * DH);
    uint4* c1 = (uint4*)(ctx + (size_t)(2 * b) * EDIM + EDIM + h * DH);
#pragma unroll
    for (int d = 0; d < 8; d++) {
        uint4 va = v0[d], vb = v1[d];
        const __half2* pa = (const __half2*)&va;
        const __half2* pb = (const __half2*)&vb;
        uint4 o0, o1;
        __half2* po0 = (__half2*)&o0;
        __half2* po1 = (__half2*)&o1;
#pragma unroll
        for (int i = 0; i < 4; i++) {
            float2 x = __half22float2(pa[i]);
            float2 y = __half22float2(pb[i]);
            po0[i] = __floats2half2_rn(a00 * x.x + a01 * y.x, a00 * x.y + a01 * y.y);
            po1[i] = __floats2half2_rn(a10 * x.x + a11 * y.x, a10 * x.y + a11 * y.y);
        }
        c0[d] = o0;
        c1[d] = o1;
    }

    // mean over heads: 8 consecutive lanes share a b
    float w0 = a00, w1 = a01, w2 = a10, w3 = a11;
#pragma unroll
    for (int off = 4; off >= 1; off >>= 1) {
        w0 += __shfl_xor_sync(0xffffffffu, w0, off);
        w1 += __shfl_xor_sync(0xffffffffu, w1, off);
        w2 += __shfl_xor_sync(0xffffffffu, w2, off);
        w3 += __shfl_xor_sync(0xffffffffu, w3, off);
    }
    if (h == 0) {
        float4 w;
        w.x = w0 * 0.125f; w.y = w1 * 0.125f; w.z = w2 * 0.125f; w.w = w3 * 0.125f;
        *(float4*)(wout + (size_t)b * 4) = w;
    }
}

// ---------------- launch ----------------
extern "C" void kernel_launch(void* const* d_in, const int* in_sizes, int n_in,
                              void* d_out, int out_size) {
    const float* vis  = (const float*)d_in[0];
    const float* txt  = (const float*)d_in[1];
    const float* wqkv = (const float*)d_in[2];
    const float* bqkv = (const float*)d_in[3];
    const float* wo   = (const float*)d_in[4];
    const float* bo   = (const float*)d_in[5];
    const float* w1   = (const float*)d_in[6];
    const float* b1   = (const float*)d_in[7];
    const float* w2   = (const float*)d_in[8];
    const float* b2   = (const float*)d_in[9];
    const float* gam  = (const float*)d_in[10];
    const float* bet  = (const float*)d_in[11];

    float* out     = (float*)d_out;
    float* fused   = out;                               // B x 256
    float* weights = out + (size_t)BATCH * OUTD;        // B x 4

    __half *p_x, *p_qkv, *p_ctx, *p_h, *p_w, *p_woT, *p_wf;
    float *p_bf, *p_zb;
    cudaGetSymbolAddress((void**)&p_x,   g_x);
    cudaGetSymbolAddress((void**)&p_qkv, g_qkv);
    cudaGetSymbolAddress((void**)&p_ctx, g_ctx);
    cudaGetSymbolAddress((void**)&p_h,   g_h);
    cudaGetSymbolAddress((void**)&p_w,   g_w);
    cudaGetSymbolAddress((void**)&p_woT, g_woT);
    cudaGetSymbolAddress((void**)&p_wf,  g_wf);
    cudaGetSymbolAddress((void**)&p_bf,  g_bf);
    cudaGetSymbolAddress((void**)&p_zb,  g_zb);

    cudaFuncSetAttribute(tc_gemm<0,1>, cudaFuncAttributeMaxDynamicSharedMemorySize, SMEM_BYTES);
    cudaFuncSetAttribute(tc_gemm<1,1>, cudaFuncAttributeMaxDynamicSharedMemorySize, SMEM_BYTES);
    cudaFuncSetAttribute(tc_gemm_ln, cudaFuncAttributeMaxDynamicSharedMemorySize, SMEM4_BYTES);

    // 0) pre-convert weights + build interleaved fp16 input + fused weight prep
    cvt_kernel<<<(QKVN * EDIM / 4 + 255) / 256, 256>>>(wqkv, p_w + W_QKV, QKVN * EDIM / 4);
    cvt_kernel<<<(HIDD * CONCATD / 4 + 255) / 256, 256>>>(w1, p_w + W_1, HIDD * CONCATD / 4);
    cvt_kernel<<<(OUTD * HIDD / 4 + 255) / 256, 256>>>(w2, p_w + W_2, OUTD * HIDD / 4);
    transpose_wo<<<(EDIM * EDIM) / 256, 256>>>(wo, p_woT);
    interleave_kernel<<<(size_t)ROWS2 * EDIM / 4 / 256, 256>>>(vis, txt, p_x);
    bfused_kernel<<<(HIDD + 255) / 256, 256>>>(w1, bo, b1, p_bf);

    // 0b) Wf[:, s*512 + e] = W1[:, s*512:(s+1)*512] @ Wo   (s = 0, 1), fp16 out
    tc_gemm<0,1><<<dim3(4, 4), 256, SMEM_BYTES>>>(
        p_w + W_1, p_woT, p_zb, p_wf, CONCATD, CONCATD, EDIM);
    tc_gemm<0,1><<<dim3(4, 4), 256, SMEM_BYTES>>>(
        p_w + W_1 + 512, p_woT, p_zb, p_wf + 512, CONCATD, CONCATD, EDIM);

    // 1) QKV = X @ Wqkv^T + b        (2B x 1536, fp16 out)
    tc_gemm<0,1><<<dim3(QKVN / 128, ROWS2 / 128), 256, SMEM_BYTES>>>(
        p_x, p_w + W_QKV, bqkv, p_qkv, EDIM, QKVN, EDIM);

    // 2) attention -> ctx (fp16, B x 1024 view) + weights (B x 4)
    attn_kernel<<<(BATCH * NH) / 256, 256>>>(p_qkv, p_ctx, weights);

    // 3) H = gelu(ctx2 @ Wf^T + bf)   (B x 512, fp16 out)  [out-proj folded in]
    tc_gemm<1,1><<<dim3(HIDD / 128, BATCH / 128), 256, SMEM_BYTES>>>(
        p_ctx, p_wf, p_bf, p_h, CONCATD, HIDD, CONCATD);

    // 4) fused = LN(H @ W2^T + b2) * gamma + beta   (B x 256, fp32 out)
    tc_gemm_ln<<<BATCH / 128, 256, SMEM4_BYTES>>>(
        p_h, p_w + W_2, b2, gam, bet, fused);
}

// round 16
// speedup vs baseline: 1.3947x; 1.0027x over previous
#include <cuda_runtime.h>
#include <cuda_fp16.h>
#include <math.h>
#include <stdint.h>

// ---------------- problem dims ----------------
#define BATCH   65536
#define EDIM    512
#define NH      8
#define DH      64
#define ROWS2   (2*BATCH)      // 131072 sequence rows
#define QKVN    1536
#define CONCATD 1024
#define HIDD    512
#define OUTD    256

// ---------------- scratch (no allocations allowed) ----------------
__device__ __half g_x  [(size_t)ROWS2 * EDIM];   // interleaved fp16 input
__device__ __half g_qkv[(size_t)ROWS2 * QKVN];   // 2B x 1536
__device__ __half g_ctx[(size_t)ROWS2 * EDIM];   // 2B x 512 == B x 1024 (ctx2)
__device__ __half g_h  [(size_t)BATCH * HIDD];   // B x 512
// fp16 weights, concatenated
#define W_QKV 0
#define W_1   1048576
#define W_2   1572864
__device__ __half g_w[1703936];
__device__ __half g_woT[EDIM * EDIM];            // Wo^T fp16 (512x512)
__device__ __half g_wf [HIDD * CONCATD];         // fused W1@Wo2 (512x1024)
__device__ float  g_bf [HIDD];                   // fused bias
__device__ float  g_zb [EDIM];                   // zero bias (never written)

// ---------------- PTX helpers ----------------
__device__ __forceinline__ uint32_t smem_u32(const void* p) {
    uint32_t a;
    asm("{ .reg .u64 t; cvta.to.shared.u64 t, %1; cvt.u32.u64 %0, t; }" : "=r"(a) : "l"(p));
    return a;
}
__device__ __forceinline__ void cp16(uint32_t dst, const void* src) {
    asm volatile("cp.async.cg.shared.global [%0], [%1], 16;" :: "r"(dst), "l"(src));
}
#define CP_COMMIT() asm volatile("cp.async.commit_group;" ::: "memory")
#define CP_WAIT(n)  asm volatile("cp.async.wait_group %0;" :: "n"(n) : "memory")

__device__ __forceinline__ void ldsm4(uint32_t& r0, uint32_t& r1, uint32_t& r2, uint32_t& r3,
                                      uint32_t addr) {
    asm volatile("ldmatrix.sync.aligned.m8n8.x4.shared.b16 {%0,%1,%2,%3}, [%4];"
                 : "=r"(r0), "=r"(r1), "=r"(r2), "=r"(r3) : "r"(addr));
}

// D += A*B  (m16n8k16, f16 in, f32 accum)
__device__ __forceinline__ void mma_f16(float* d, const uint32_t* a, const uint32_t* b) {
    asm volatile(
        "mma.sync.aligned.m16n8k16.row.col.f32.f16.f16.f32 "
        "{%0,%1,%2,%3}, {%4,%5,%6,%7}, {%8,%9}, {%0,%1,%2,%3};"
        : "+f"(d[0]), "+f"(d[1]), "+f"(d[2]), "+f"(d[3])
        : "r"(a[0]), "r"(a[1]), "r"(a[2]), "r"(a[3]), "r"(b[0]), "r"(b[1]));
}

// ---------------- pre-convert kernels ----------------
__global__ __launch_bounds__(256)
void cvt_kernel(const float* __restrict__ in, __half* __restrict__ out, int n4) {
    int i = blockIdx.x * 256 + threadIdx.x;
    if (i >= n4) return;
    float4 v = *((const float4*)in + i);
    __half2 h0 = __floats2half2_rn(v.x, v.y);
    __half2 h1 = __floats2half2_rn(v.z, v.w);
    __half2* dst = (__half2*)(out + (size_t)i * 4);
    dst[0] = h0;
    dst[1] = h1;
}

// interleave vis/txt into g_x (rows alternate), converting to fp16
__global__ __launch_bounds__(256)
void interleave_kernel(const float* __restrict__ vis, const float* __restrict__ txt,
                       __half* __restrict__ out) {
    int i = blockIdx.x * 256 + threadIdx.x;      // float4 index
    int grow = i >> 7;                            // 128 float4 per row
    int j = i & 127;
    const float* src = (grow & 1) ? txt : vis;
    float4 v = *((const float4*)(src + (size_t)(grow >> 1) * EDIM) + j);
    __half2 h0 = __floats2half2_rn(v.x, v.y);
    __half2 h1 = __floats2half2_rn(v.z, v.w);
    __half2* dst = (__half2*)(out + (size_t)grow * EDIM + j * 4);
    dst[0] = h0;
    dst[1] = h1;
}

// transpose Wo (512x512 f32, torch (out,in)) -> WoT fp16 : WoT[e][j] = Wo[j][e]
__global__ __launch_bounds__(256)
void transpose_wo(const float* __restrict__ wo, __half* __restrict__ woT) {
    int i = blockIdx.x * 256 + threadIdx.x;   // output index e*512 + j
    int e = i >> 9;
    int j = i & 511;
    woT[i] = __float2half_rn(wo[j * EDIM + e]);
}

// fused bias: bf[n] = b1[n] + sum_m W1[n][m] * bo[m % 512]   (all fp32)
__global__ __launch_bounds__(256)
void bfused_kernel(const float* __restrict__ w1, const float* __restrict__ bo,
                   const float* __restrict__ b1, float* __restrict__ bf) {
    int n = blockIdx.x * 256 + threadIdx.x;
    if (n >= HIDD) return;
    const float* row = w1 + (size_t)n * CONCATD;
    float s = 0.f;
    for (int m = 0; m < CONCATD; m++) s += row[m] * bo[m & 511];
    bf[n] = b1[n] + s;
}

// ---------------- fp16 mma.sync GEMM ----------------
// C = A(row stride lda) @ W[N,K]^T + bias.  EPI=1: exact GELU.  HALFOUT: fp16.
// CTA 128x128, BK=64 halves, 3-stage cp.async (ONE barrier per K-tile),
// 8 warps (2x4), warp tile 64x32, ldmatrix.x4.
// B fragments double-buffered across kk; A fragments pipelined across mt.
#define PADKH 72                       // 64 + 8 halves per smem row (144B)
#define A_HALF (128 * PADKH)           // per operand per stage
#define STG_HALF (2 * A_HALF)
#define STG_BYTES (STG_HALF * 2)       // 36864
#define NSTAGE 3
#define SMEM_BYTES (NSTAGE * STG_BYTES)   // 110592

template <int EPI, int HALFOUT>
__global__ __launch_bounds__(256, 2)
void tc_gemm(const __half* __restrict__ A, const __half* __restrict__ W,
             const float* __restrict__ bias, void* __restrict__ Cv,
             int lda, int ldc, int K) {
    extern __shared__ __half smem[];
    const uint32_t smem_u = smem_u32(smem);

    const int tid = threadIdx.x;
    const int wid = tid >> 5;
    const int lane = tid & 31;
    const int g  = lane >> 2;      // 0..7
    const int t4 = lane & 3;       // 0..3
    const int wm = (wid >> 2) * 64;   // warp row base
    const int wn = (wid & 3) * 32;    // warp col base
    const int m0 = blockIdx.y * 128;
    const int n0 = blockIdx.x * 128;

    const uint32_t aLane = ((uint32_t)(wm + (lane & 15)) * PADKH + ((lane >> 4) & 1) * 8) * 2;
    const uint32_t bLane = ((uint32_t)(wn + (lane & 7) + ((lane >> 4) & 1) * 8) * PADKH
                            + ((lane >> 3) & 1) * 8) * 2 + A_HALF * 2;

    const int lrow = tid >> 1;
    const int lhalf = (tid & 1) * 32;
    const __half* aPtr = A + (size_t)(m0 + lrow) * lda + lhalf;
    const __half* bPtr = W + (size_t)(n0 + lrow) * K + lhalf;
    const uint32_t aDst = smem_u + (lrow * PADKH + lhalf) * 2;
    const uint32_t bDst = aDst + A_HALF * 2;

    float acc[4][4][4];
#pragma unroll
    for (int i = 0; i < 4; i++)
#pragma unroll
        for (int j = 0; j < 4; j++)
#pragma unroll
            for (int r = 0; r < 4; r++) acc[i][j][r] = 0.f;

    const int KT = K >> 6;   // K / 64

#pragma unroll
    for (int s = 0; s < NSTAGE - 1; s++) {
        const __half* ap = aPtr + s * 64;
        const __half* bp = bPtr + s * 64;
        const uint32_t aD = aDst + s * STG_BYTES;
        const uint32_t bD = bDst + s * STG_BYTES;
#pragma unroll
        for (int i = 0; i < 4; i++) cp16(aD + i * 16, ap + i * 8);
#pragma unroll
        for (int i = 0; i < 4; i++) cp16(bD + i * 16, bp + i * 8);
        CP_COMMIT();
    }

    int s = 0;
    for (int kt = 0; kt < KT; kt++) {
        if (kt + 1 < KT) { CP_WAIT(1); } else { CP_WAIT(0); }
        __syncthreads();

        if (kt + 2 < KT) {
            int spre = s + 2; if (spre >= NSTAGE) spre -= NSTAGE;
            const __half* ap = aPtr + (kt + 2) * 64;
            const __half* bp = bPtr + (kt + 2) * 64;
            const uint32_t aD = aDst + spre * STG_BYTES;
            const uint32_t bD = bDst + spre * STG_BYTES;
#pragma unroll
            for (int i = 0; i < 4; i++) cp16(aD + i * 16, ap + i * 8);
#pragma unroll
            for (int i = 0; i < 4; i++) cp16(bD + i * 16, bp + i * 8);
            CP_COMMIT();
        }

        const uint32_t aBase = smem_u + s * STG_BYTES + aLane;
        const uint32_t bBase = smem_u + s * STG_BYTES + bLane;

        // B fragments double-buffered across kk; A fragments pipelined per mt.
        uint32_t bf[2][4][2];
        uint32_t af[2][4];
        ldsm4(bf[0][0][0], bf[0][0][1], bf[0][1][0], bf[0][1][1], bBase);
        ldsm4(bf[0][2][0], bf[0][2][1], bf[0][3][0], bf[0][3][1],
              bBase + 16 * PADKH * 2);
#pragma unroll
        for (int kk = 0; kk < 4; kk++) {
            const int cur = kk & 1, nxt = cur ^ 1;
            const uint32_t kOff = kk * 32;
            ldsm4(af[0][0], af[0][1], af[0][2], af[0][3], aBase + kOff);
            if (kk < 3) {
                const uint32_t kn = (kk + 1) * 32;
                ldsm4(bf[nxt][0][0], bf[nxt][0][1], bf[nxt][1][0], bf[nxt][1][1],
                      bBase + kn);
                ldsm4(bf[nxt][2][0], bf[nxt][2][1], bf[nxt][3][0], bf[nxt][3][1],
                      bBase + 16 * PADKH * 2 + kn);
            }
#pragma unroll
            for (int mt = 0; mt < 4; mt++) {
                const int ca = mt & 1, na = ca ^ 1;
                if (mt < 3)
                    ldsm4(af[na][0], af[na][1], af[na][2], af[na][3],
                          aBase + (mt + 1) * (16 * PADKH * 2) + kOff);
#pragma unroll
                for (int nt = 0; nt < 4; nt++)
                    mma_f16(acc[mt][nt], af[ca], bf[cur][nt]);
            }
        }

        s++; if (s == NSTAGE) s = 0;
    }

#pragma unroll
    for (int mt = 0; mt < 4; mt++) {
        const size_t r0 = (size_t)(m0 + wm + mt * 16 + g);
        const size_t r1 = r0 + 8;
#pragma unroll
        for (int nt = 0; nt < 4; nt++) {
            const int col = n0 + wn + nt * 8 + t4 * 2;
            const float b0 = __ldg(bias + col);
            const float b1 = __ldg(bias + col + 1);
            float2 v0, v1;
            v0.x = acc[mt][nt][0] + b0;  v0.y = acc[mt][nt][1] + b1;
            v1.x = acc[mt][nt][2] + b0;  v1.y = acc[mt][nt][3] + b1;
            if (EPI == 1) {
                v0.x = 0.5f * v0.x * (1.0f + erff(v0.x * 0.70710678118654752f));
                v0.y = 0.5f * v0.y * (1.0f + erff(v0.y * 0.70710678118654752f));
                v1.x = 0.5f * v1.x * (1.0f + erff(v1.x * 0.70710678118654752f));
                v1.y = 0.5f * v1.y * (1.0f + erff(v1.y * 0.70710678118654752f));
            }
            if (HALFOUT) {
                __half* C = (__half*)Cv;
                *(__half2*)(C + r0 * ldc + col) = __floats2half2_rn(v0.x, v0.y);
                *(__half2*)(C + r1 * ldc + col) = __floats2half2_rn(v1.x, v1.y);
            } else {
                float* C = (float*)Cv;
                *(float2*)(C + r0 * ldc + col) = v0;
                *(float2*)(C + r1 * ldc + col) = v1;
            }
        }
    }
}

// ---------------- GEMM4 + LayerNorm fused ----------------
// out[B,256] = LN(H @ W2^T + b2) * gamma + beta.  CTA 128x256 (full LN width),
// 8 warps (2m x 4n), warp tile 64x64.  K = 512.
#define A4_HALF (128 * PADKH)
#define B4_HALF (256 * PADKH)
#define STG4_HALF (A4_HALF + B4_HALF)
#define STG4_BYTES (STG4_HALF * 2)        // 55296
#define SMEM4_BYTES (NSTAGE * STG4_BYTES) // 165888

__global__ __launch_bounds__(256, 1)
void tc_gemm_ln(const __half* __restrict__ A, const __half* __restrict__ W,
                const float* __restrict__ bias, const float* __restrict__ gamma,
                const float* __restrict__ beta, float* __restrict__ out) {
    extern __shared__ __half smem[];
    const uint32_t smem_u = smem_u32(smem);
    const int K = HIDD;      // 512
    const int tid = threadIdx.x;
    const int wid = tid >> 5;
    const int lane = tid & 31;
    const int g  = lane >> 2;
    const int t4 = lane & 3;
    const int wm = (wid >> 2) * 64;   // 0/64
    const int wn = (wid & 3) * 64;    // 0..192
    const int m0 = blockIdx.x * 128;

    const uint32_t aLane = ((uint32_t)(wm + (lane & 15)) * PADKH + ((lane >> 4) & 1) * 8) * 2;
    const uint32_t bLane = ((uint32_t)(wn + (lane & 7) + ((lane >> 4) & 1) * 8) * PADKH
                            + ((lane >> 3) & 1) * 8) * 2 + A4_HALF * 2;

    const int arow = tid >> 1;
    const int ahalf = (tid & 1) * 32;
    const __half* aPtr = A + (size_t)(m0 + arow) * K + ahalf;
    const __half* bPtr = W + (size_t)tid * K;
    const uint32_t aDst = smem_u + (arow * PADKH + ahalf) * 2;
    const uint32_t bDst = smem_u + A4_HALF * 2 + (tid * PADKH) * 2;

    float acc[4][8][4];
#pragma unroll
    for (int i = 0; i < 4; i++)
#pragma unroll
        for (int j = 0; j < 8; j++)
#pragma unroll
            for (int r = 0; r < 4; r++) acc[i][j][r] = 0.f;

    const int KT = K >> 6;   // 8

#pragma unroll
    for (int s = 0; s < NSTAGE - 1; s++) {
        const __half* ap = aPtr + s * 64;
        const __half* bp = bPtr + s * 64;
        const uint32_t aD = aDst + s * STG4_BYTES;
        const uint32_t bD = bDst + s * STG4_BYTES;
#pragma unroll
        for (int i = 0; i < 4; i++) cp16(aD + i * 16, ap + i * 8);
#pragma unroll
        for (int i = 0; i < 8; i++) cp16(bD + i * 16, bp + i * 8);
        CP_COMMIT();
    }

    int s = 0;
    for (int kt = 0; kt < KT; kt++) {
        if (kt + 1 < KT) { CP_WAIT(1); } else { CP_WAIT(0); }
        __syncthreads();

        if (kt + 2 < KT) {
            int spre = s + 2; if (spre >= NSTAGE) spre -= NSTAGE;
            const __half* ap = aPtr + (kt + 2) * 64;
            const __half* bp = bPtr + (kt + 2) * 64;
            const uint32_t aD = aDst + spre * STG4_BYTES;
            const uint32_t bD = bDst + spre * STG4_BYTES;
#pragma unroll
            for (int i = 0; i < 4; i++) cp16(aD + i * 16, ap + i * 8);
#pragma unroll
            for (int i = 0; i < 8; i++) cp16(bD + i * 16, bp + i * 8);
            CP_COMMIT();
        }

        const uint32_t aBase = smem_u + s * STG4_BYTES + aLane;
        const uint32_t bBase = smem_u + s * STG4_BYTES + bLane;

#pragma unroll
        for (int kk = 0; kk < 4; kk++) {
            const uint32_t kOff = kk * 32;
            uint32_t af[4][4], bf[8][2];
#pragma unroll
            for (int mt = 0; mt < 4; mt++)
                ldsm4(af[mt][0], af[mt][1], af[mt][2], af[mt][3],
                      aBase + mt * (16 * PADKH * 2) + kOff);
#pragma unroll
            for (int j = 0; j < 4; j++)
                ldsm4(bf[2 * j][0], bf[2 * j][1], bf[2 * j + 1][0], bf[2 * j + 1][1],
                      bBase + j * (16 * PADKH * 2) + kOff);
#pragma unroll
            for (int mt = 0; mt < 4; mt++)
#pragma unroll
                for (int nt = 0; nt < 8; nt++)
                    mma_f16(acc[mt][nt], af[mt], bf[nt]);
        }

        s++; if (s == NSTAGE) s = 0;
    }

    // ---- fused LayerNorm epilogue ----
    __syncthreads();
    float* rs1 = (float*)smem;            // [128][4]
    float* rs2 = rs1 + 128 * 4;           // [128][4]
    const int wnIdx = wid & 3;

#pragma unroll
    for (int mt = 0; mt < 4; mt++) {
        float s1a = 0.f, s2a = 0.f, s1b = 0.f, s2b = 0.f;
#pragma unroll
        for (int nt = 0; nt < 8; nt++) {
            const int col = wn + nt * 8 + t4 * 2;
            const float b0 = __ldg(bias + col);
            const float b1 = __ldg(bias + col + 1);
            acc[mt][nt][0] += b0; acc[mt][nt][1] += b1;
            acc[mt][nt][2] += b0; acc[mt][nt][3] += b1;
            s1a += acc[mt][nt][0] + acc[mt][nt][1];
            s2a += acc[mt][nt][0] * acc[mt][nt][0] + acc[mt][nt][1] * acc[mt][nt][1];
            s1b += acc[mt][nt][2] + acc[mt][nt][3];
            s2b += acc[mt][nt][2] * acc[mt][nt][2] + acc[mt][nt][3] * acc[mt][nt][3];
        }
#pragma unroll
        for (int off = 1; off <= 2; off <<= 1) {
            s1a += __shfl_xor_sync(0xffffffffu, s1a, off);
            s2a += __shfl_xor_sync(0xffffffffu, s2a, off);
            s1b += __shfl_xor_sync(0xffffffffu, s1b, off);
            s2b += __shfl_xor_sync(0xffffffffu, s2b, off);
        }
        if (t4 == 0) {
            const int r0 = wm + mt * 16 + g;
            rs1[r0 * 4 + wnIdx] = s1a;  rs2[r0 * 4 + wnIdx] = s2a;
            rs1[(r0 + 8) * 4 + wnIdx] = s1b;  rs2[(r0 + 8) * 4 + wnIdx] = s2b;
        }
    }
    __syncthreads();

#pragma unroll
    for (int mt = 0; mt < 4; mt++) {
        const int r0 = wm + mt * 16 + g;
        const int r1 = r0 + 8;
        float su0 = rs1[r0 * 4] + rs1[r0 * 4 + 1] + rs1[r0 * 4 + 2] + rs1[r0 * 4 + 3];
        float sq0 = rs2[r0 * 4] + rs2[r0 * 4 + 1] + rs2[r0 * 4 + 2] + rs2[r0 * 4 + 3];
        float su1 = rs1[r1 * 4] + rs1[r1 * 4 + 1] + rs1[r1 * 4 + 2] + rs1[r1 * 4 + 3];
        float sq1 = rs2[r1 * 4] + rs2[r1 * 4 + 1] + rs2[r1 * 4 + 2] + rs2[r1 * 4 + 3];
        const float mu0 = su0 * (1.0f / OUTD);
        const float iv0 = rsqrtf(sq0 * (1.0f / OUTD) - mu0 * mu0 + 1e-5f);
        const float mu1 = su1 * (1.0f / OUTD);
        const float iv1 = rsqrtf(sq1 * (1.0f / OUTD) - mu1 * mu1 + 1e-5f);
        float* o0 = out + (size_t)(m0 + r0) * OUTD;
        float* o1 = out + (size_t)(m0 + r1) * OUTD;
#pragma unroll
        for (int nt = 0; nt < 8; nt++) {
            const int col = wn + nt * 8 + t4 * 2;
            const float ga0 = __ldg(gamma + col), ga1 = __ldg(gamma + col + 1);
            const float be0 = __ldg(beta + col),  be1 = __ldg(beta + col + 1);
            float2 v0, v1;
            v0.x = (acc[mt][nt][0] - mu0) * iv0 * ga0 + be0;
            v0.y = (acc[mt][nt][1] - mu0) * iv0 * ga1 + be1;
            v1.x = (acc[mt][nt][2] - mu1) * iv1 * ga0 + be0;
            v1.y = (acc[mt][nt][3] - mu1) * iv1 * ga1 + be1;
            *(float2*)(o0 + col) = v0;
            *(float2*)(o1 + col) = v1;
        }
    }
}

// ---------------- attention: one thread per (b, h); 16B vectorized ----------
__device__ __forceinline__ float dot8h(uint4 a, uint4 b) {
    float s = 0.f;
    const __half2* pa = (const __half2*)&a;
    const __half2* pb = (const __half2*)&b;
#pragma unroll
    for (int i = 0; i < 4; i++) {
        float2 x = __half22float2(pa[i]);
        float2 y = __half22float2(pb[i]);
        s += x.x * y.x + x.y * y.y;
    }
    return s;
}

__global__ __launch_bounds__(256)
void attn_kernel(const __half* __restrict__ qkv, __half* __restrict__ ctx,
                 float* __restrict__ wout) {
    int t = blockIdx.x * blockDim.x + threadIdx.x;   // b*8 + h
    int b = t >> 3;
    int h = t & 7;

    const __half* base = qkv + (size_t)(2 * b) * QKVN + h * DH;
    const uint4* q0 = (const uint4*)(base);
    const uint4* q1 = (const uint4*)(base + QKVN);
    const uint4* k0 = (const uint4*)(base + 512);
    const uint4* k1 = (const uint4*)(base + 512 + QKVN);
    const uint4* v0 = (const uint4*)(base + 1024);
    const uint4* v1 = (const uint4*)(base + 1024 + QKVN);

    float s00 = 0.f, s01 = 0.f, s10 = 0.f, s11 = 0.f;
#pragma unroll
    for (int d = 0; d < 8; d++) {
        uint4 qa = q0[d], qb = q1[d], ka = k0[d], kb = k1[d];
        s00 += dot8h(qa, ka);
        s01 += dot8h(qa, kb);
        s10 += dot8h(qb, ka);
        s11 += dot8h(qb, kb);
    }
    const float sc = 0.125f;   // 1/sqrt(64)
    s00 *= sc; s01 *= sc; s10 *= sc; s11 *= sc;

    float m0 = fmaxf(s00, s01);
    float e00 = expf(s00 - m0), e01 = expf(s01 - m0);
    float r0 = 1.0f / (e00 + e01);
    float a00 = e00 * r0, a01 = e01 * r0;

    float m1 = fmaxf(s10, s11);
    float e10 = expf(s10 - m1), e11 = expf(s11 - m1);
    float r1 = 1.0f / (e10 + e11);
    float a10 = e10 * r1, a11 = e11 * r1;

    uint4* c0 = (uint4*)(ctx + (size_t)(2 * b) * EDIM + h * DH);
    uint4* c1 = (uint4*)(ctx + (size_t)(2 * b) * EDIM + EDIM + h * DH);
#pragma unroll
    for (int d = 0; d < 8; d++) {
        uint4 va = v0[d], vb = v1[d];
        const __half2* pa = (const __half2*)&va;
        const __half2* pb = (const __half2*)&vb;
        uint4 o0, o1;
        __half2* po0 = (__half2*)&o0;
        __half2* po1 = (__half2*)&o1;
#pragma unroll
        for (int i = 0; i < 4; i++) {
            float2 x = __half22float2(pa[i]);
            float2 y = __half22float2(pb[i]);
            po0[i] = __floats2half2_rn(a00 * x.x + a01 * y.x, a00 * x.y + a01 * y.y);
            po1[i] = __floats2half2_rn(a10 * x.x + a11 * y.x, a10 * x.y + a11 * y.y);
        }
        c0[d] = o0;
        c1[d] = o1;
    }

    // mean over heads: 8 consecutive lanes share a b
    float w0 = a00, w1 = a01, w2 = a10, w3 = a11;
#pragma unroll
    for (int off = 4; off >= 1; off >>= 1) {
        w0 += __shfl_xor_sync(0xffffffffu, w0, off);
        w1 += __shfl_xor_sync(0xffffffffu, w1, off);
        w2 += __shfl_xor_sync(0xffffffffu, w2, off);
        w3 += __shfl_xor_sync(0xffffffffu, w3, off);
    }
    if (h == 0) {
        float4 w;
        w.x = w0 * 0.125f; w.y = w1 * 0.125f; w.z = w2 * 0.125f; w.w = w3 * 0.125f;
        *(float4*)(wout + (size_t)b * 4) = w;
    }
}

// ---------------- launch ----------------
extern "C" void kernel_launch(void* const* d_in, const int* in_sizes, int n_in,
                              void* d_out, int out_size) {
    const float* vis  = (const float*)d_in[0];
    const float* txt  = (const float*)d_in[1];
    const float* wqkv = (const float*)d_in[2];
    const float* bqkv = (const float*)d_in[3];
    const float* wo   = (const float*)d_in[4];
    const float* bo   = (const float*)d_in[5];
    const float* w1   = (const float*)d_in[6];
    const float* b1   = (const float*)d_in[7];
    const float* w2   = (const float*)d_in[8];
    const float* b2   = (const float*)d_in[9];
    const float* gam  = (const float*)d_in[10];
    const float* bet  = (const float*)d_in[11];

    float* out     = (float*)d_out;
    float* fused   = out;                               // B x 256
    float* weights = out + (size_t)BATCH * OUTD;        // B x 4

    __half *p_x, *p_qkv, *p_ctx, *p_h, *p_w, *p_woT, *p_wf;
    float *p_bf, *p_zb;
    cudaGetSymbolAddress((void**)&p_x,   g_x);
    cudaGetSymbolAddress((void**)&p_qkv, g_qkv);
    cudaGetSymbolAddress((void**)&p_ctx, g_ctx);
    cudaGetSymbolAddress((void**)&p_h,   g_h);
    cudaGetSymbolAddress((void**)&p_w,   g_w);
    cudaGetSymbolAddress((void**)&p_woT, g_woT);
    cudaGetSymbolAddress((void**)&p_wf,  g_wf);
    cudaGetSymbolAddress((void**)&p_bf,  g_bf);
    cudaGetSymbolAddress((void**)&p_zb,  g_zb);

    cudaFuncSetAttribute(tc_gemm<0,1>, cudaFuncAttributeMaxDynamicSharedMemorySize, SMEM_BYTES);
    cudaFuncSetAttribute(tc_gemm<1,1>, cudaFuncAttributeMaxDynamicSharedMemorySize, SMEM_BYTES);
    cudaFuncSetAttribute(tc_gemm_ln, cudaFuncAttributeMaxDynamicSharedMemorySize, SMEM4_BYTES);

    // 0) pre-convert weights + build interleaved fp16 input + fused weight prep
    cvt_kernel<<<(QKVN * EDIM / 4 + 255) / 256, 256>>>(wqkv, p_w + W_QKV, QKVN * EDIM / 4);
    cvt_kernel<<<(HIDD * CONCATD / 4 + 255) / 256, 256>>>(w1, p_w + W_1, HIDD * CONCATD / 4);
    cvt_kernel<<<(OUTD * HIDD / 4 + 255) / 256, 256>>>(w2, p_w + W_2, OUTD * HIDD / 4);
    transpose_wo<<<(EDIM * EDIM) / 256, 256>>>(wo, p_woT);
    interleave_kernel<<<(size_t)ROWS2 * EDIM / 4 / 256, 256>>>(vis, txt, p_x);
    bfused_kernel<<<(HIDD + 255) / 256, 256>>>(w1, bo, b1, p_bf);

    // 0b) Wf[:, s*512 + e] = W1[:, s*512:(s+1)*512] @ Wo   (s = 0, 1), fp16 out
    tc_gemm<0,1><<<dim3(4, 4), 256, SMEM_BYTES>>>(
        p_w + W_1, p_woT, p_zb, p_wf, CONCATD, CONCATD, EDIM);
    tc_gemm<0,1><<<dim3(4, 4), 256, SMEM_BYTES>>>(
        p_w + W_1 + 512, p_woT, p_zb, p_wf + 512, CONCATD, CONCATD, EDIM);

    // 1) QKV = X @ Wqkv^T + b        (2B x 1536, fp16 out)
    tc_gemm<0,1><<<dim3(QKVN / 128, ROWS2 / 128), 256, SMEM_BYTES>>>(
        p_x, p_w + W_QKV, bqkv, p_qkv, EDIM, QKVN, EDIM);

    // 2) attention -> ctx (fp16, B x 1024 view) + weights (B x 4)
    attn_kernel<<<(BATCH * NH) / 256, 256>>>(p_qkv, p_ctx, weights);

    // 3) H = gelu(ctx2 @ Wf^T + bf)   (B x 512, fp16 out)  [out-proj folded in]
    tc_gemm<1,1><<<dim3(HIDD / 128, BATCH / 128), 256, SMEM_BYTES>>>(
        p_ctx, p_wf, p_bf, p_h, CONCATD, HIDD, CONCATD);

    // 4) fused = LN(H @ W2^T + b2) * gamma + beta   (B x 256, fp32 out)
    tc_gemm_ln<<<BATCH / 128, 256, SMEM4_BYTES>>>(
        p_h, p_w + W_2, b2, gam, bet, fused);
}

// round 17
// speedup vs baseline: 1.5146x; 1.0860x over previous
#include <cuda_runtime.h>
#include <cuda_fp16.h>
#include <math.h>
#include <stdint.h>

// ---------------- problem dims ----------------
#define BATCH   65536
#define EDIM    512
#define NH      8
#define DH      64
#define ROWS2   (2*BATCH)      // 131072 sequence rows
#define QKVN    1536
#define CONCATD 1024
#define HIDD    512
#define OUTD    256

// ---------------- scratch (no allocations allowed) ----------------
__device__ __half g_x  [(size_t)ROWS2 * EDIM];   // interleaved fp16 input
__device__ __half g_qkv[(size_t)ROWS2 * QKVN];   // 2B x 1536
__device__ __half g_ctx[(size_t)ROWS2 * EDIM];   // 2B x 512 == B x 1024 (ctx2)
__device__ __half g_h  [(size_t)BATCH * HIDD];   // B x 512
// fp16 weights, concatenated
#define W_QKV 0
#define W_1   1048576
#define W_2   1572864
__device__ __half g_w[1703936];
__device__ __half g_woT[EDIM * EDIM];            // Wo^T fp16 (512x512)
__device__ __half g_wf [HIDD * CONCATD];         // fused W1@Wo2 (512x1024)
__device__ float  g_bf [HIDD];                   // fused bias
__device__ float  g_zb [EDIM];                   // zero bias (never written)

// ---------------- PTX helpers ----------------
__device__ __forceinline__ uint32_t smem_u32(const void* p) {
    uint32_t a;
    asm("{ .reg .u64 t; cvta.to.shared.u64 t, %1; cvt.u32.u64 %0, t; }" : "=r"(a) : "l"(p));
    return a;
}
__device__ __forceinline__ void cp16(uint32_t dst, const void* src) {
    asm volatile("cp.async.cg.shared.global [%0], [%1], 16;" :: "r"(dst), "l"(src));
}
#define CP_COMMIT() asm volatile("cp.async.commit_group;" ::: "memory")
#define CP_WAIT(n)  asm volatile("cp.async.wait_group %0;" :: "n"(n) : "memory")

__device__ __forceinline__ void ldsm4(uint32_t& r0, uint32_t& r1, uint32_t& r2, uint32_t& r3,
                                      uint32_t addr) {
    asm volatile("ldmatrix.sync.aligned.m8n8.x4.shared.b16 {%0,%1,%2,%3}, [%4];"
                 : "=r"(r0), "=r"(r1), "=r"(r2), "=r"(r3) : "r"(addr));
}

// D += A*B  (m16n8k16, f16 in, f32 accum)
__device__ __forceinline__ void mma_f16(float* d, const uint32_t* a, const uint32_t* b) {
    asm volatile(
        "mma.sync.aligned.m16n8k16.row.col.f32.f16.f16.f32 "
        "{%0,%1,%2,%3}, {%4,%5,%6,%7}, {%8,%9}, {%0,%1,%2,%3};"
        : "+f"(d[0]), "+f"(d[1]), "+f"(d[2]), "+f"(d[3])
        : "r"(a[0]), "r"(a[1]), "r"(a[2]), "r"(a[3]), "r"(b[0]), "r"(b[1]));
}

// ---------------- pre-convert kernels ----------------
__global__ __launch_bounds__(256)
void cvt_kernel(const float* __restrict__ in, __half* __restrict__ out, int n4) {
    int i = blockIdx.x * 256 + threadIdx.x;
    if (i >= n4) return;
    float4 v = *((const float4*)in + i);
    __half2 h0 = __floats2half2_rn(v.x, v.y);
    __half2 h1 = __floats2half2_rn(v.z, v.w);
    __half2* dst = (__half2*)(out + (size_t)i * 4);
    dst[0] = h0;
    dst[1] = h1;
}

// interleave vis/txt into g_x (rows alternate), converting to fp16
__global__ __launch_bounds__(256)
void interleave_kernel(const float* __restrict__ vis, const float* __restrict__ txt,
                       __half* __restrict__ out) {
    int i = blockIdx.x * 256 + threadIdx.x;      // float4 index
    int grow = i >> 7;                            // 128 float4 per row
    int j = i & 127;
    const float* src = (grow & 1) ? txt : vis;
    float4 v = *((const float4*)(src + (size_t)(grow >> 1) * EDIM) + j);
    __half2 h0 = __floats2half2_rn(v.x, v.y);
    __half2 h1 = __floats2half2_rn(v.z, v.w);
    __half2* dst = (__half2*)(out + (size_t)grow * EDIM + j * 4);
    dst[0] = h0;
    dst[1] = h1;
}

// transpose Wo (512x512 f32, torch (out,in)) -> WoT fp16 : WoT[e][j] = Wo[j][e]
__global__ __launch_bounds__(256)
void transpose_wo(const float* __restrict__ wo, __half* __restrict__ woT) {
    int i = blockIdx.x * 256 + threadIdx.x;   // output index e*512 + j
    int e = i >> 9;
    int j = i & 511;
    woT[i] = __float2half_rn(wo[j * EDIM + e]);
}

// fused bias: bf[n] = b1[n] + sum_m W1[n][m] * bo[m % 512]
// one block per n, coalesced reads, block reduction
__global__ __launch_bounds__(256)
void bfused_kernel(const float* __restrict__ w1, const float* __restrict__ bo,
                   const float* __restrict__ b1, float* __restrict__ bf) {
    __shared__ float red[256];
    const int n = blockIdx.x;
    const int j = threadIdx.x;
    const float* row = w1 + (size_t)n * CONCATD;
    float s = 0.f;
#pragma unroll
    for (int m = j; m < CONCATD; m += 256) s += row[m] * bo[m & 511];
    red[j] = s;
    __syncthreads();
#pragma unroll
    for (int st = 128; st > 0; st >>= 1) {
        if (j < st) red[j] += red[j + st];
        __syncthreads();
    }
    if (j == 0) bf[n] = b1[n] + red[0];
}

// ---------------- fp16 mma.sync GEMM ----------------
// C = A(row stride lda) @ W[N,K]^T + bias.  EPI=1: exact GELU.  HALFOUT: fp16.
// CTA 128x128, BK=64 halves, 3-stage cp.async (ONE barrier per K-tile),
// 8 warps (2x4), warp tile 64x32, ldmatrix.x4.
// B fragments double-buffered across kk; A fragments pipelined across mt.
#define PADKH 72                       // 64 + 8 halves per smem row (144B)
#define A_HALF (128 * PADKH)           // per operand per stage
#define STG_HALF (2 * A_HALF)
#define STG_BYTES (STG_HALF * 2)       // 36864
#define NSTAGE 3
#define SMEM_BYTES (NSTAGE * STG_BYTES)   // 110592

template <int EPI, int HALFOUT>
__global__ __launch_bounds__(256, 2)
void tc_gemm(const __half* __restrict__ A, const __half* __restrict__ W,
             const float* __restrict__ bias, void* __restrict__ Cv,
             int lda, int ldc, int K) {
    extern __shared__ __half smem[];
    const uint32_t smem_u = smem_u32(smem);

    const int tid = threadIdx.x;
    const int wid = tid >> 5;
    const int lane = tid & 31;
    const int g  = lane >> 2;      // 0..7
    const int t4 = lane & 3;       // 0..3
    const int wm = (wid >> 2) * 64;   // warp row base
    const int wn = (wid & 3) * 32;    // warp col base
    const int m0 = blockIdx.y * 128;
    const int n0 = blockIdx.x * 128;

    const uint32_t aLane = ((uint32_t)(wm + (lane & 15)) * PADKH + ((lane >> 4) & 1) * 8) * 2;
    const uint32_t bLane = ((uint32_t)(wn + (lane & 7) + ((lane >> 4) & 1) * 8) * PADKH
                            + ((lane >> 3) & 1) * 8) * 2 + A_HALF * 2;

    const int lrow = tid >> 1;
    const int lhalf = (tid & 1) * 32;
    const __half* aPtr = A + (size_t)(m0 + lrow) * lda + lhalf;
    const __half* bPtr = W + (size_t)(n0 + lrow) * K + lhalf;
    const uint32_t aDst = smem_u + (lrow * PADKH + lhalf) * 2;
    const uint32_t bDst = aDst + A_HALF * 2;

    float acc[4][4][4];
#pragma unroll
    for (int i = 0; i < 4; i++)
#pragma unroll
        for (int j = 0; j < 4; j++)
#pragma unroll
            for (int r = 0; r < 4; r++) acc[i][j][r] = 0.f;

    const int KT = K >> 6;   // K / 64

#pragma unroll
    for (int s = 0; s < NSTAGE - 1; s++) {
        const __half* ap = aPtr + s * 64;
        const __half* bp = bPtr + s * 64;
        const uint32_t aD = aDst + s * STG_BYTES;
        const uint32_t bD = bDst + s * STG_BYTES;
#pragma unroll
        for (int i = 0; i < 4; i++) cp16(aD + i * 16, ap + i * 8);
#pragma unroll
        for (int i = 0; i < 4; i++) cp16(bD + i * 16, bp + i * 8);
        CP_COMMIT();
    }

    int s = 0;
    for (int kt = 0; kt < KT; kt++) {
        if (kt + 1 < KT) { CP_WAIT(1); } else { CP_WAIT(0); }
        __syncthreads();

        if (kt + 2 < KT) {
            int spre = s + 2; if (spre >= NSTAGE) spre -= NSTAGE;
            const __half* ap = aPtr + (kt + 2) * 64;
            const __half* bp = bPtr + (kt + 2) * 64;
            const uint32_t aD = aDst + spre * STG_BYTES;
            const uint32_t bD = bDst + spre * STG_BYTES;
#pragma unroll
            for (int i = 0; i < 4; i++) cp16(aD + i * 16, ap + i * 8);
#pragma unroll
            for (int i = 0; i < 4; i++) cp16(bD + i * 16, bp + i * 8);
            CP_COMMIT();
        }

        const uint32_t aBase = smem_u + s * STG_BYTES + aLane;
        const uint32_t bBase = smem_u + s * STG_BYTES + bLane;

        // B fragments double-buffered across kk; A fragments pipelined per mt.
        uint32_t bf[2][4][2];
        uint32_t af[2][4];
        ldsm4(bf[0][0][0], bf[0][0][1], bf[0][1][0], bf[0][1][1], bBase);
        ldsm4(bf[0][2][0], bf[0][2][1], bf[0][3][0], bf[0][3][1],
              bBase + 16 * PADKH * 2);
#pragma unroll
        for (int kk = 0; kk < 4; kk++) {
            const int cur = kk & 1, nxt = cur ^ 1;
            const uint32_t kOff = kk * 32;
            ldsm4(af[0][0], af[0][1], af[0][2], af[0][3], aBase + kOff);
            if (kk < 3) {
                const uint32_t kn = (kk + 1) * 32;
                ldsm4(bf[nxt][0][0], bf[nxt][0][1], bf[nxt][1][0], bf[nxt][1][1],
                      bBase + kn);
                ldsm4(bf[nxt][2][0], bf[nxt][2][1], bf[nxt][3][0], bf[nxt][3][1],
                      bBase + 16 * PADKH * 2 + kn);
            }
#pragma unroll
            for (int mt = 0; mt < 4; mt++) {
                const int ca = mt & 1, na = ca ^ 1;
                if (mt < 3)
                    ldsm4(af[na][0], af[na][1], af[na][2], af[na][3],
                          aBase + (mt + 1) * (16 * PADKH * 2) + kOff);
#pragma unroll
                for (int nt = 0; nt < 4; nt++)
                    mma_f16(acc[mt][nt], af[ca], bf[cur][nt]);
            }
        }

        s++; if (s == NSTAGE) s = 0;
    }

#pragma unroll
    for (int mt = 0; mt < 4; mt++) {
        const size_t r0 = (size_t)(m0 + wm + mt * 16 + g);
        const size_t r1 = r0 + 8;
#pragma unroll
        for (int nt = 0; nt < 4; nt++) {
            const int col = n0 + wn + nt * 8 + t4 * 2;
            const float b0 = __ldg(bias + col);
            const float b1 = __ldg(bias + col + 1);
            float2 v0, v1;
            v0.x = acc[mt][nt][0] + b0;  v0.y = acc[mt][nt][1] + b1;
            v1.x = acc[mt][nt][2] + b0;  v1.y = acc[mt][nt][3] + b1;
            if (EPI == 1) {
                v0.x = 0.5f * v0.x * (1.0f + erff(v0.x * 0.70710678118654752f));
                v0.y = 0.5f * v0.y * (1.0f + erff(v0.y * 0.70710678118654752f));
                v1.x = 0.5f * v1.x * (1.0f + erff(v1.x * 0.70710678118654752f));
                v1.y = 0.5f * v1.y * (1.0f + erff(v1.y * 0.70710678118654752f));
            }
            if (HALFOUT) {
                __half* C = (__half*)Cv;
                *(__half2*)(C + r0 * ldc + col) = __floats2half2_rn(v0.x, v0.y);
                *(__half2*)(C + r1 * ldc + col) = __floats2half2_rn(v1.x, v1.y);
            } else {
                float* C = (float*)Cv;
                *(float2*)(C + r0 * ldc + col) = v0;
                *(float2*)(C + r1 * ldc + col) = v1;
            }
        }
    }
}

// ---------------- GEMM4 + LayerNorm fused ----------------
// out[B,256] = LN(H @ W2^T + b2) * gamma + beta.  CTA 128x256 (full LN width),
// 8 warps (2m x 4n), warp tile 64x64.  K = 512.
#define A4_HALF (128 * PADKH)
#define B4_HALF (256 * PADKH)
#define STG4_HALF (A4_HALF + B4_HALF)
#define STG4_BYTES (STG4_HALF * 2)        // 55296
#define SMEM4_BYTES (NSTAGE * STG4_BYTES) // 165888

__global__ __launch_bounds__(256, 1)
void tc_gemm_ln(const __half* __restrict__ A, const __half* __restrict__ W,
                const float* __restrict__ bias, const float* __restrict__ gamma,
                const float* __restrict__ beta, float* __restrict__ out) {
    extern __shared__ __half smem[];
    const uint32_t smem_u = smem_u32(smem);
    const int K = HIDD;      // 512
    const int tid = threadIdx.x;
    const int wid = tid >> 5;
    const int lane = tid & 31;
    const int g  = lane >> 2;
    const int t4 = lane & 3;
    const int wm = (wid >> 2) * 64;   // 0/64
    const int wn = (wid & 3) * 64;    // 0..192
    const int m0 = blockIdx.x * 128;

    const uint32_t aLane = ((uint32_t)(wm + (lane & 15)) * PADKH + ((lane >> 4) & 1) * 8) * 2;
    const uint32_t bLane = ((uint32_t)(wn + (lane & 7) + ((lane >> 4) & 1) * 8) * PADKH
                            + ((lane >> 3) & 1) * 8) * 2 + A4_HALF * 2;

    const int arow = tid >> 1;
    const int ahalf = (tid & 1) * 32;
    const __half* aPtr = A + (size_t)(m0 + arow) * K + ahalf;
    const __half* bPtr = W + (size_t)tid * K;
    const uint32_t aDst = smem_u + (arow * PADKH + ahalf) * 2;
    const uint32_t bDst = smem_u + A4_HALF * 2 + (tid * PADKH) * 2;

    float acc[4][8][4];
#pragma unroll
    for (int i = 0; i < 4; i++)
#pragma unroll
        for (int j = 0; j < 8; j++)
#pragma unroll
            for (int r = 0; r < 4; r++) acc[i][j][r] = 0.f;

    const int KT = K >> 6;   // 8

#pragma unroll
    for (int s = 0; s < NSTAGE - 1; s++) {
        const __half* ap = aPtr + s * 64;
        const __half* bp = bPtr + s * 64;
        const uint32_t aD = aDst + s * STG4_BYTES;
        const uint32_t bD = bDst + s * STG4_BYTES;
#pragma unroll
        for (int i = 0; i < 4; i++) cp16(aD + i * 16, ap + i * 8);
#pragma unroll
        for (int i = 0; i < 8; i++) cp16(bD + i * 16, bp + i * 8);
        CP_COMMIT();
    }

    int s = 0;
    for (int kt = 0; kt < KT; kt++) {
        if (kt + 1 < KT) { CP_WAIT(1); } else { CP_WAIT(0); }
        __syncthreads();

        if (kt + 2 < KT) {
            int spre = s + 2; if (spre >= NSTAGE) spre -= NSTAGE;
            const __half* ap = aPtr + (kt + 2) * 64;
            const __half* bp = bPtr + (kt + 2) * 64;
            const uint32_t aD = aDst + spre * STG4_BYTES;
            const uint32_t bD = bDst + spre * STG4_BYTES;
#pragma unroll
            for (int i = 0; i < 4; i++) cp16(aD + i * 16, ap + i * 8);
#pragma unroll
            for (int i = 0; i < 8; i++) cp16(bD + i * 16, bp + i * 8);
            CP_COMMIT();
        }

        const uint32_t aBase = smem_u + s * STG4_BYTES + aLane;
        const uint32_t bBase = smem_u + s * STG4_BYTES + bLane;

#pragma unroll
        for (int kk = 0; kk < 4; kk++) {
            const uint32_t kOff = kk * 32;
            uint32_t af[4][4], bf[8][2];
#pragma unroll
            for (int mt = 0; mt < 4; mt++)
                ldsm4(af[mt][0], af[mt][1], af[mt][2], af[mt][3],
                      aBase + mt * (16 * PADKH * 2) + kOff);
#pragma unroll
            for (int j = 0; j < 4; j++)
                ldsm4(bf[2 * j][0], bf[2 * j][1], bf[2 * j + 1][0], bf[2 * j + 1][1],
                      bBase + j * (16 * PADKH * 2) + kOff);
#pragma unroll
            for (int mt = 0; mt < 4; mt++)
#pragma unroll
                for (int nt = 0; nt < 8; nt++)
                    mma_f16(acc[mt][nt], af[mt], bf[nt]);
        }

        s++; if (s == NSTAGE) s = 0;
    }

    // ---- fused LayerNorm epilogue ----
    __syncthreads();
    float* rs1 = (float*)smem;            // [128][4]
    float* rs2 = rs1 + 128 * 4;           // [128][4]
    const int wnIdx = wid & 3;

#pragma unroll
    for (int mt = 0; mt < 4; mt++) {
        float s1a = 0.f, s2a = 0.f, s1b = 0.f, s2b = 0.f;
#pragma unroll
        for (int nt = 0; nt < 8; nt++) {
            const int col = wn + nt * 8 + t4 * 2;
            const float b0 = __ldg(bias + col);
            const float b1 = __ldg(bias + col + 1);
            acc[mt][nt][0] += b0; acc[mt][nt][1] += b1;
            acc[mt][nt][2] += b0; acc[mt][nt][3] += b1;
            s1a += acc[mt][nt][0] + acc[mt][nt][1];
            s2a += acc[mt][nt][0] * acc[mt][nt][0] + acc[mt][nt][1] * acc[mt][nt][1];
            s1b += acc[mt][nt][2] + acc[mt][nt][3];
            s2b += acc[mt][nt][2] * acc[mt][nt][2] + acc[mt][nt][3] * acc[mt][nt][3];
        }
#pragma unroll
        for (int off = 1; off <= 2; off <<= 1) {
            s1a += __shfl_xor_sync(0xffffffffu, s1a, off);
            s2a += __shfl_xor_sync(0xffffffffu, s2a, off);
            s1b += __shfl_xor_sync(0xffffffffu, s1b, off);
            s2b += __shfl_xor_sync(0xffffffffu, s2b, off);
        }
        if (t4 == 0) {
            const int r0 = wm + mt * 16 + g;
            rs1[r0 * 4 + wnIdx] = s1a;  rs2[r0 * 4 + wnIdx] = s2a;
            rs1[(r0 + 8) * 4 + wnIdx] = s1b;  rs2[(r0 + 8) * 4 + wnIdx] = s2b;
        }
    }
    __syncthreads();

#pragma unroll
    for (int mt = 0; mt < 4; mt++) {
        const int r0 = wm + mt * 16 + g;
        const int r1 = r0 + 8;
        float su0 = rs1[r0 * 4] + rs1[r0 * 4 + 1] + rs1[r0 * 4 + 2] + rs1[r0 * 4 + 3];
        float sq0 = rs2[r0 * 4] + rs2[r0 * 4 + 1] + rs2[r0 * 4 + 2] + rs2[r0 * 4 + 3];
        float su1 = rs1[r1 * 4] + rs1[r1 * 4 + 1] + rs1[r1 * 4 + 2] + rs1[r1 * 4 + 3];
        float sq1 = rs2[r1 * 4] + rs2[r1 * 4 + 1] + rs2[r1 * 4 + 2] + rs2[r1 * 4 + 3];
        const float mu0 = su0 * (1.0f / OUTD);
        const float iv0 = rsqrtf(sq0 * (1.0f / OUTD) - mu0 * mu0 + 1e-5f);
        const float mu1 = su1 * (1.0f / OUTD);
        const float iv1 = rsqrtf(sq1 * (1.0f / OUTD) - mu1 * mu1 + 1e-5f);
        float* o0 = out + (size_t)(m0 + r0) * OUTD;
        float* o1 = out + (size_t)(m0 + r1) * OUTD;
#pragma unroll
        for (int nt = 0; nt < 8; nt++) {
            const int col = wn + nt * 8 + t4 * 2;
            const float ga0 = __ldg(gamma + col), ga1 = __ldg(gamma + col + 1);
            const float be0 = __ldg(beta + col),  be1 = __ldg(beta + col + 1);
            float2 v0, v1;
            v0.x = (acc[mt][nt][0] - mu0) * iv0 * ga0 + be0;
            v0.y = (acc[mt][nt][1] - mu0) * iv0 * ga1 + be1;
            v1.x = (acc[mt][nt][2] - mu1) * iv1 * ga0 + be0;
            v1.y = (acc[mt][nt][3] - mu1) * iv1 * ga1 + be1;
            *(float2*)(o0 + col) = v0;
            *(float2*)(o1 + col) = v1;
        }
    }
}

// ---------------- attention: one thread per (b, h); 16B vectorized ----------
__device__ __forceinline__ float dot8h(uint4 a, uint4 b) {
    float s = 0.f;
    const __half2* pa = (const __half2*)&a;
    const __half2* pb = (const __half2*)&b;
#pragma unroll
    for (int i = 0; i < 4; i++) {
        float2 x = __half22float2(pa[i]);
        float2 y = __half22float2(pb[i]);
        s += x.x * y.x + x.y * y.y;
    }
    return s;
}

__global__ __launch_bounds__(256)
void attn_kernel(const __half* __restrict__ qkv, __half* __restrict__ ctx,
                 float* __restrict__ wout) {
    int t = blockIdx.x * blockDim.x + threadIdx.x;   // b*8 + h
    int b = t >> 3;
    int h = t & 7;

    const __half* base = qkv + (size_t)(2 * b) * QKVN + h * DH;
    const uint4* q0 = (const uint4*)(base);
    const uint4* q1 = (const uint4*)(base + QKVN);
    const uint4* k0 = (const uint4*)(base + 512);
    const uint4* k1 = (const uint4*)(base + 512 + QKVN);
    const uint4* v0 = (const uint4*)(base + 1024);
    const uint4* v1 = (const uint4*)(base + 1024 + QKVN);

    float s00 = 0.f, s01 = 0.f, s10 = 0.f, s11 = 0.f;
#pragma unroll
    for (int d = 0; d < 8; d++) {
        uint4 qa = q0[d], qb = q1[d], ka = k0[d], kb = k1[d];
        s00 += dot8h(qa, ka);
        s01 += dot8h(qa, kb);
        s10 += dot8h(qb, ka);
        s11 += dot8h(qb, kb);
    }
    const float sc = 0.125f;   // 1/sqrt(64)
    s00 *= sc; s01 *= sc; s10 *= sc; s11 *= sc;

    float m0 = fmaxf(s00, s01);
    float e00 = expf(s00 - m0), e01 = expf(s01 - m0);
    float r0 = 1.0f / (e00 + e01);
    float a00 = e00 * r0, a01 = e01 * r0;

    float m1 = fmaxf(s10, s11);
    float e10 = expf(s10 - m1), e11 = expf(s11 - m1);
    float r1 = 1.0f / (e10 + e11);
    float a10 = e10 * r1, a11 = e11 * r1;

    uint4* c0 = (uint4*)(ctx + (size_t)(2 * b) * EDIM + h * DH);
    uint4* c1 = (uint4*)(ctx + (size_t)(2 * b) * EDIM + EDIM + h * DH);
#pragma unroll
    for (int d = 0; d < 8; d++) {
        uint4 va = v0[d], vb = v1[d];
        const __half2* pa = (const __half2*)&va;
        const __half2* pb = (const __half2*)&vb;
        uint4 o0, o1;
        __half2* po0 = (__half2*)&o0;
        __half2* po1 = (__half2*)&o1;
#pragma unroll
        for (int i = 0; i < 4; i++) {
            float2 x = __half22float2(pa[i]);
            float2 y = __half22float2(pb[i]);
            po0[i] = __floats2half2_rn(a00 * x.x + a01 * y.x, a00 * x.y + a01 * y.y);
            po1[i] = __floats2half2_rn(a10 * x.x + a11 * y.x, a10 * x.y + a11 * y.y);
        }
        c0[d] = o0;
        c1[d] = o1;
    }

    // mean over heads: 8 consecutive lanes share a b
    float w0 = a00, w1 = a01, w2 = a10, w3 = a11;
#pragma unroll
    for (int off = 4; off >= 1; off >>= 1) {
        w0 += __shfl_xor_sync(0xffffffffu, w0, off);
        w1 += __shfl_xor_sync(0xffffffffu, w1, off);
        w2 += __shfl_xor_sync(0xffffffffu, w2, off);
        w3 += __shfl_xor_sync(0xffffffffu, w3, off);
    }
    if (h == 0) {
        float4 w;
        w.x = w0 * 0.125f; w.y = w1 * 0.125f; w.z = w2 * 0.125f; w.w = w3 * 0.125f;
        *(float4*)(wout + (size_t)b * 4) = w;
    }
}

// ---------------- launch ----------------
extern "C" void kernel_launch(void* const* d_in, const int* in_sizes, int n_in,
                              void* d_out, int out_size) {
    const float* vis  = (const float*)d_in[0];
    const float* txt  = (const float*)d_in[1];
    const float* wqkv = (const float*)d_in[2];
    const float* bqkv = (const float*)d_in[3];
    const float* wo   = (const float*)d_in[4];
    const float* bo   = (const float*)d_in[5];
    const float* w1   = (const float*)d_in[6];
    const float* b1   = (const float*)d_in[7];
    const float* w2   = (const float*)d_in[8];
    const float* b2   = (const float*)d_in[9];
    const float* gam  = (const float*)d_in[10];
    const float* bet  = (const float*)d_in[11];

    float* out     = (float*)d_out;
    float* fused   = out;                               // B x 256
    float* weights = out + (size_t)BATCH * OUTD;        // B x 4

    __half *p_x, *p_qkv, *p_ctx, *p_h, *p_w, *p_woT, *p_wf;
    float *p_bf, *p_zb;
    cudaGetSymbolAddress((void**)&p_x,   g_x);
    cudaGetSymbolAddress((void**)&p_qkv, g_qkv);
    cudaGetSymbolAddress((void**)&p_ctx, g_ctx);
    cudaGetSymbolAddress((void**)&p_h,   g_h);
    cudaGetSymbolAddress((void**)&p_w,   g_w);
    cudaGetSymbolAddress((void**)&p_woT, g_woT);
    cudaGetSymbolAddress((void**)&p_wf,  g_wf);
    cudaGetSymbolAddress((void**)&p_bf,  g_bf);
    cudaGetSymbolAddress((void**)&p_zb,  g_zb);

    cudaFuncSetAttribute(tc_gemm<0,1>, cudaFuncAttributeMaxDynamicSharedMemorySize, SMEM_BYTES);
    cudaFuncSetAttribute(tc_gemm<1,1>, cudaFuncAttributeMaxDynamicSharedMemorySize, SMEM_BYTES);
    cudaFuncSetAttribute(tc_gemm_ln, cudaFuncAttributeMaxDynamicSharedMemorySize, SMEM4_BYTES);

    // 1-3) minimal QKV dependencies, then QKV as 4th launch (profiler target)
    cvt_kernel<<<(QKVN * EDIM / 4 + 255) / 256, 256>>>(wqkv, p_w + W_QKV, QKVN * EDIM / 4);
    interleave_kernel<<<(size_t)ROWS2 * EDIM / 4 / 256, 256>>>(vis, txt, p_x);
    cvt_kernel<<<(HIDD * CONCATD / 4 + 255) / 256, 256>>>(w1, p_w + W_1, HIDD * CONCATD / 4);

    // 4) QKV = X @ Wqkv^T + b        (2B x 1536, fp16 out)
    tc_gemm<0,1><<<dim3(QKVN / 128, ROWS2 / 128), 256, SMEM_BYTES>>>(
        p_x, p_w + W_QKV, bqkv, p_qkv, EDIM, QKVN, EDIM);

    // 5+) remaining prep (independent of QKV output)
    cvt_kernel<<<(OUTD * HIDD / 4 + 255) / 256, 256>>>(w2, p_w + W_2, OUTD * HIDD / 4);
    transpose_wo<<<(EDIM * EDIM) / 256, 256>>>(wo, p_woT);
    bfused_kernel<<<HIDD, 256>>>(w1, bo, b1, p_bf);
    tc_gemm<0,1><<<dim3(4, 4), 256, SMEM_BYTES>>>(
        p_w + W_1, p_woT, p_zb, p_wf, CONCATD, CONCATD, EDIM);
    tc_gemm<0,1><<<dim3(4, 4), 256, SMEM_BYTES>>>(
        p_w + W_1 + 512, p_woT, p_zb, p_wf + 512, CONCATD, CONCATD, EDIM);

    // attention -> ctx (fp16, B x 1024 view) + weights (B x 4)
    attn_kernel<<<(BATCH * NH) / 256, 256>>>(p_qkv, p_ctx, weights);

    // H = gelu(ctx2 @ Wf^T + bf)   (B x 512, fp16 out)  [out-proj folded in]
    tc_gemm<1,1><<<dim3(HIDD / 128, BATCH / 128), 256, SMEM_BYTES>>>(
        p_ctx, p_wf, p_bf, p_h, CONCATD, HIDD, CONCATD);

    // fused = LN(H @ W2^T + b2) * gamma + beta   (B x 256, fp32 out)
    tc_gemm_ln<<<BATCH / 128, 256, SMEM4_BYTES>>>(
        p_h, p_w + W_2, b2, gam, bet, fused);
}